// round 4
// baseline (speedup 1.0000x reference)
#include <cuda_runtime.h>
#include <math.h>

#define S_LEN 2048
#define DHEAD 128
#define NHEAD 8
#define NB 2
#define WIN 511
#define QK_SCALE 0.08838834764831845f   // 1/sqrt(128)

// Projected Q/K/V scratch: [B][H][S][D] fp32, 16 MB each (static device arrays, no allocs)
__device__ float g_Qp[NB*NHEAD*S_LEN*DHEAD];
__device__ float g_Kp[NB*NHEAD*S_LEN*DHEAD];
__device__ float g_Vp[NB*NHEAD*S_LEN*DHEAD];

// ---------------------------------------------------------------------------
// Projection GEMM: C[4096,1024] = X[4096,128] @ W[128,1024], scattered to
// [b][h][s][d] layout. blockIdx.z selects which of the 3 projections.
// Tile 64x64, full K=128 in smem, 4x4 microtile per thread (256 threads).
// ---------------------------------------------------------------------------
__global__ __launch_bounds__(256, 3) void proj_kernel(
    const float* __restrict__ q, const float* __restrict__ k, const float* __restrict__ v,
    const float* __restrict__ Wq, const float* __restrict__ Wk, const float* __restrict__ Wv)
{
    extern __shared__ float sm[];
    float* As = sm;          // [128][64]  k-major (transposed A)
    float* Bs = sm + 8192;   // [128][64]
    const float *X, *W; float* O;
    if (blockIdx.z == 0)      { X = q; W = Wq; O = g_Qp; }
    else if (blockIdx.z == 1) { X = k; W = Wk; O = g_Kp; }
    else                      { X = v; W = Wv; O = g_Vp; }

    int m0 = blockIdx.x << 6;   // [0,4096)
    int n0 = blockIdx.y << 6;   // [0,1024)
    int tid = threadIdx.x;

    // Load A tile (64 rows x 128 k) transposed into As[k][m]
    {
        int r  = tid >> 2;
        int kc = (tid & 3) << 5;
        const float* src = X + (size_t)(m0 + r) * DHEAD + kc;
        #pragma unroll
        for (int i = 0; i < 8; i++) {
            float4 a = *(const float4*)(src + i * 4);
            int kk = kc + i * 4;
            As[(kk+0)*64 + r] = a.x;
            As[(kk+1)*64 + r] = a.y;
            As[(kk+2)*64 + r] = a.z;
            As[(kk+3)*64 + r] = a.w;
        }
        // Load B tile (128 k x 64 n) directly (already k-major)
        #pragma unroll
        for (int i = 0; i < 8; i++) {
            int l  = tid + i * 256;
            int kk = l >> 4;
            int c4 = (l & 15) << 2;
            *(float4*)(Bs + kk*64 + c4) = *(const float4*)(W + (size_t)kk * 1024 + n0 + c4);
        }
    }
    __syncthreads();

    int tx = tid & 15, ty = tid >> 4;
    float acc[4][4] = {};
    #pragma unroll 16
    for (int kk = 0; kk < 128; kk++) {
        float4 a  = *(const float4*)(As + kk*64 + (ty << 2));
        float4 bb = *(const float4*)(Bs + kk*64 + (tx << 2));
        float av[4] = {a.x, a.y, a.z, a.w};
        float bv[4] = {bb.x, bb.y, bb.z, bb.w};
        #pragma unroll
        for (int i = 0; i < 4; i++)
            #pragma unroll
            for (int j = 0; j < 4; j++)
                acc[i][j] = fmaf(av[i], bv[j], acc[i][j]);
    }

    // Scatter-store to [b][h][s][d]; n-tile never crosses a head boundary.
    int n = n0 + (tx << 2);
    int h = n >> 7, dd = n & 127;
    #pragma unroll
    for (int i = 0; i < 4; i++) {
        int m = m0 + (ty << 2) + i;
        int b = m >> 11, s = m & 2047;
        *(float4*)(O + (((size_t)(b*NHEAD + h) * S_LEN + s) * DHEAD + dd)) =
            make_float4(acc[i][0], acc[i][1], acc[i][2], acc[i][3]);
    }
}

// ---------------------------------------------------------------------------
// Windowed flash attention. CTA = (query tile of 64, head, batch).
// Key tiles of 64 from (qs-511)>>6 up to the diagonal tile. Exact reference
// arithmetic for masks: j>i -> -2e9; j<=i outside window -> qk*scale - 1e9;
// in-window -> qk*scale + emb[i-j-1]. Masked exps underflow to 0 exactly.
// ---------------------------------------------------------------------------
__global__ __launch_bounds__(256, 2) void attn_kernel(
    const float* __restrict__ emb, float* __restrict__ out)
{
    extern __shared__ float sm[];
    float* Qs      = sm;                 // [128][64] k-major
    float* KVs     = sm + 8192;          // K as [128][64], then reused as V [64][128]
    float* Ss      = sm + 16384;         // [64][65] scores -> probs
    float* emb_s   = sm + 16384 + 64*65; // 512
    float* alpha_s = emb_s + 512;        // 64
    float* l_s     = alpha_s + 64;       // 64

    int qt = blockIdx.x, h = blockIdx.y, b = blockIdx.z;
    int qs = qt << 6;
    int tid = threadIdx.x;
    size_t headoff = (size_t)(b*NHEAD + h) * S_LEN * DHEAD;
    const float* Qh = g_Qp + headoff;
    const float* Kh = g_Kp + headoff;
    const float* Vh = g_Vp + headoff;

    for (int i = tid; i < 512; i += 256) emb_s[i] = emb[i];

    // Load Q tile transposed into Qs[k][m]
    {
        int r  = tid >> 2;
        int kc = (tid & 3) << 5;
        const float* src = Qh + (size_t)(qs + r) * DHEAD + kc;
        #pragma unroll
        for (int i = 0; i < 8; i++) {
            float4 a = *(const float4*)(src + i * 4);
            int kk = kc + i * 4;
            Qs[(kk+0)*64 + r] = a.x;
            Qs[(kk+1)*64 + r] = a.y;
            Qs[(kk+2)*64 + r] = a.z;
            Qs[(kk+3)*64 + r] = a.w;
        }
    }

    int tx = tid & 15, ty = tid >> 4;     // QK map: 4x4 microtile
    int srow = tid >> 2, sg = tid & 3;    // softmax map: 4 lanes per row
    int rg = tid >> 4, cg = tid & 15;     // PV map: rows 4*rg.., cols 8*cg..

    float m_run = -INFINITY, l_run = 0.f;
    float Oacc[4][8];
    #pragma unroll
    for (int i = 0; i < 4; i++)
        #pragma unroll
        for (int c = 0; c < 8; c++) Oacc[i][c] = 0.f;

    int kt_lo = (qs >= WIN) ? ((qs - WIN) >> 6) : 0;

    for (int kt = kt_lo; kt <= qt; kt++) {
        int ks0 = kt << 6;
        __syncthreads();   // prev PV done reading KVs/Ss (also gates first-iter Qs/emb)

        // Load K tile transposed into KVs[k][m]
        {
            int r  = tid >> 2;
            int kc = (tid & 3) << 5;
            const float* src = Kh + (size_t)(ks0 + r) * DHEAD + kc;
            #pragma unroll
            for (int i = 0; i < 8; i++) {
                float4 a = *(const float4*)(src + i * 4);
                int kk = kc + i * 4;
                KVs[(kk+0)*64 + r] = a.x;
                KVs[(kk+1)*64 + r] = a.y;
                KVs[(kk+2)*64 + r] = a.z;
                KVs[(kk+3)*64 + r] = a.w;
            }
        }
        __syncthreads();

        // --- QK^T (64x64, K=128), fused bias/mask, write to Ss ---
        float acc[4][4] = {};
        #pragma unroll 16
        for (int kk = 0; kk < 128; kk++) {
            float4 a  = *(const float4*)(Qs  + kk*64 + (ty << 2));
            float4 bb = *(const float4*)(KVs + kk*64 + (tx << 2));
            float av[4] = {a.x, a.y, a.z, a.w};
            float bv[4] = {bb.x, bb.y, bb.z, bb.w};
            #pragma unroll
            for (int i = 0; i < 4; i++)
                #pragma unroll
                for (int j = 0; j < 4; j++)
                    acc[i][j] = fmaf(av[i], bv[j], acc[i][j]);
        }
        #pragma unroll
        for (int i = 0; i < 4; i++) {
            int ig = qs + (ty << 2) + i;
            #pragma unroll
            for (int j = 0; j < 4; j++) {
                int jg = ks0 + (tx << 2) + j;
                float s;
                if (jg > ig) {
                    s = -2e9f;                      // causal(-1e9) + rpe(-1e9)
                } else {
                    int dd = ig - jg;
                    s = acc[i][j] * QK_SCALE +
                        ((dd >= 1 && dd <= WIN) ? emb_s[dd - 1] : -1e9f);
                }
                Ss[((ty << 2) + i) * 65 + (tx << 2) + j] = s;
            }
        }
        __syncthreads();

        // Prefetch V tile into registers (overlaps softmax); KVs still holds K
        // but QK is done, so we can overwrite after softmax.
        float4 vreg[8];
        int vr = tid >> 2, vc = (tid & 3) << 5;
        {
            const float* src = Vh + (size_t)(ks0 + vr) * DHEAD + vc;
            #pragma unroll
            for (int i = 0; i < 8; i++) vreg[i] = *(const float4*)(src + i * 4);
        }

        // --- online softmax (4 lanes per row, shfl reductions) ---
        {
            float vals[16];
            float mx = -INFINITY;
            #pragma unroll
            for (int j = 0; j < 16; j++) {
                vals[j] = Ss[srow*65 + (sg << 4) + j];
                mx = fmaxf(mx, vals[j]);
            }
            mx = fmaxf(mx, __shfl_xor_sync(0xffffffffu, mx, 1));
            mx = fmaxf(mx, __shfl_xor_sync(0xffffffffu, mx, 2));
            float m_new = fmaxf(m_run, mx);
            float alpha = __expf(m_run - m_new);   // 0 on first real tile (m_run=-inf)
            float lsum = 0.f;
            #pragma unroll
            for (int j = 0; j < 16; j++) {
                float p = __expf(vals[j] - m_new); // masked -> underflow to exactly 0
                Ss[srow*65 + (sg << 4) + j] = p;
                lsum += p;
            }
            lsum += __shfl_xor_sync(0xffffffffu, lsum, 1);
            lsum += __shfl_xor_sync(0xffffffffu, lsum, 2);
            l_run = fmaf(l_run, alpha, lsum);
            m_run = m_new;
            if (sg == 0) { alpha_s[srow] = alpha; l_s[srow] = l_run; }
        }

        // Store V into KVs as [j][c]
        {
            float* dst = KVs + vr * DHEAD + vc;
            #pragma unroll
            for (int i = 0; i < 8; i++) *(float4*)(dst + i * 4) = vreg[i];
        }
        __syncthreads();

        // --- PV: O = O*alpha + P @ V (4 rows x 8 cols per thread) ---
        {
            float a0 = alpha_s[(rg << 2) + 0];
            float a1 = alpha_s[(rg << 2) + 1];
            float a2 = alpha_s[(rg << 2) + 2];
            float a3 = alpha_s[(rg << 2) + 3];
            #pragma unroll
            for (int c = 0; c < 8; c++) {
                Oacc[0][c] *= a0; Oacc[1][c] *= a1;
                Oacc[2][c] *= a2; Oacc[3][c] *= a3;
            }
            #pragma unroll 4
            for (int j = 0; j < 64; j++) {
                float p0 = Ss[((rg << 2) + 0) * 65 + j];
                float p1 = Ss[((rg << 2) + 1) * 65 + j];
                float p2 = Ss[((rg << 2) + 2) * 65 + j];
                float p3 = Ss[((rg << 2) + 3) * 65 + j];
                float4 v0 = *(const float4*)(KVs + j*DHEAD + (cg << 3));
                float4 v1 = *(const float4*)(KVs + j*DHEAD + (cg << 3) + 4);
                float vv[8] = {v0.x, v0.y, v0.z, v0.w, v1.x, v1.y, v1.z, v1.w};
                #pragma unroll
                for (int c = 0; c < 8; c++) {
                    Oacc[0][c] = fmaf(p0, vv[c], Oacc[0][c]);
                    Oacc[1][c] = fmaf(p1, vv[c], Oacc[1][c]);
                    Oacc[2][c] = fmaf(p2, vv[c], Oacc[2][c]);
                    Oacc[3][c] = fmaf(p3, vv[c], Oacc[3][c]);
                }
            }
        }
    }
    __syncthreads();

    // Normalize and store: out[b][s][h*128 + c]
    #pragma unroll
    for (int i = 0; i < 4; i++) {
        int r = (rg << 2) + i;
        float inv = 1.f / l_s[r];
        float* dst = out + ((size_t)(b*S_LEN + qs + r) * (NHEAD*DHEAD)) + h*DHEAD + (cg << 3);
        *(float4*)(dst)     = make_float4(Oacc[i][0]*inv, Oacc[i][1]*inv,
                                          Oacc[i][2]*inv, Oacc[i][3]*inv);
        *(float4*)(dst + 4) = make_float4(Oacc[i][4]*inv, Oacc[i][5]*inv,
                                          Oacc[i][6]*inv, Oacc[i][7]*inv);
    }
}

extern "C" void kernel_launch(void* const* d_in, const int* in_sizes, int n_in,
                              void* d_out, int out_size)
{
    (void)in_sizes; (void)n_in; (void)out_size;
    const float* q   = (const float*)d_in[0];
    const float* k   = (const float*)d_in[1];
    const float* v   = (const float*)d_in[2];
    const float* Wq  = (const float*)d_in[3];
    const float* Wk  = (const float*)d_in[4];
    const float* Wv  = (const float*)d_in[5];
    const float* emb = (const float*)d_in[6];
    float* out = (float*)d_out;

    cudaFuncSetAttribute(proj_kernel, cudaFuncAttributeMaxDynamicSharedMemorySize, 65536);
    cudaFuncSetAttribute(attn_kernel, cudaFuncAttributeMaxDynamicSharedMemorySize, 84736);

    // 3 projections: grid (M/64, N/64, 3)
    proj_kernel<<<dim3(64, 16, 3), 256, 65536>>>(q, k, v, Wq, Wk, Wv);
    // attention: grid (S/64, H, B)
    attn_kernel<<<dim3(32, NHEAD, NB), 256, 84736>>>(emb, out);
}

// round 8
// speedup vs baseline: 2.2272x; 2.2272x over previous
#include <cuda_runtime.h>
#include <math.h>
#include <stdint.h>

#define S_LEN 2048
#define DHEAD 128
#define NHEAD 8
#define NB 2
#define WIN 511
#define QK_SCALE 0.08838834764831845f   // 1/sqrt(128)

// Projected Q/K/V scratch: [B][H][S][D] fp32 (static device arrays, no allocs)
__device__ float g_Qp[NB*NHEAD*S_LEN*DHEAD];
__device__ float g_Kp[NB*NHEAD*S_LEN*DHEAD];
__device__ float g_Vp[NB*NHEAD*S_LEN*DHEAD];

// ---------------------------------------------------------------------------
// helpers
// ---------------------------------------------------------------------------
__device__ __forceinline__ uint32_t tf32r(float x) {
    uint32_t r; asm("cvt.rn.tf32.f32 %0, %1;" : "=r"(r) : "f"(x)); return r;
}
__device__ __forceinline__ void mma8(float* c, const uint32_t* a, uint32_t b0, uint32_t b1) {
    asm("mma.sync.aligned.m16n8k8.row.col.f32.tf32.tf32.f32 "
        "{%0,%1,%2,%3}, {%4,%5,%6,%7}, {%8,%9}, {%0,%1,%2,%3};"
        : "+f"(c[0]), "+f"(c[1]), "+f"(c[2]), "+f"(c[3])
        : "r"(a[0]), "r"(a[1]), "r"(a[2]), "r"(a[3]), "r"(b0), "r"(b1));
}
__device__ __forceinline__ uint4 cvt4(float4 a) {
    return make_uint4(tf32r(a.x), tf32r(a.y), tf32r(a.z), tf32r(a.w));
}

// ---------------------------------------------------------------------------
// Projection GEMM via tf32 mma: out[b,h,s,d] = X[4096,128] @ W[128,1024]
// CTA tile 128(m) x 128(n=one head), 256 threads (8 warps x 16 rows).
// ---------------------------------------------------------------------------
#define PX_STR 132      // Xs row stride (floats): bank = g*4+t, conflict-free A frags
#define PW_STR 132      // Ws row stride (n-major): bank = g*4+t, conflict-free B frags

__global__ __launch_bounds__(256, 1) void proj_mma(
    const float* __restrict__ q, const float* __restrict__ k, const float* __restrict__ v,
    const float* __restrict__ Wq, const float* __restrict__ Wk, const float* __restrict__ Wv)
{
    extern __shared__ float sm[];
    float* Xs = sm;                    // [128][132]  row-major (m,k)
    float* Ws = sm + 128 * PX_STR;     // [128][132]  n-major   (n,k)

    const float *X, *W; float* O;
    if (blockIdx.z == 0)      { X = q; W = Wq; O = g_Qp; }
    else if (blockIdx.z == 1) { X = k; W = Wk; O = g_Kp; }
    else                      { X = v; W = Wv; O = g_Vp; }

    int m0 = blockIdx.x << 7;
    int n0 = blockIdx.y << 7;          // == head * 128
    int tid = threadIdx.x;
    int lane = tid & 31, w = tid >> 5, g = lane >> 2, t = lane & 3;

    // stage X tile (cvt to tf32)
    {
        int r = tid >> 1, kc = (tid & 1) << 6;
        const float* src = X + (size_t)(m0 + r) * DHEAD + kc;
        #pragma unroll
        for (int i = 0; i < 16; i++)
            *(uint4*)&Xs[r * PX_STR + kc + i * 4] = cvt4(*(const float4*)(src + i * 4));
    }
    // stage W tile transposed to n-major (cvt to tf32)
    {
        int kk = tid >> 1, nc = (tid & 1) << 6;
        const float* src = W + (size_t)kk * 1024 + n0 + nc;
        #pragma unroll
        for (int i = 0; i < 16; i++) {
            float4 a = *(const float4*)(src + i * 4);
            float vv[4] = {a.x, a.y, a.z, a.w};
            #pragma unroll
            for (int e = 0; e < 4; e++)
                Ws[(nc + i * 4 + e) * PW_STR + kk] = __uint_as_float(tf32r(vv[e]));
        }
    }
    __syncthreads();

    // A frags (warp's 16 rows, registers)
    uint32_t qa[16][4];
    {
        const float* ab = Xs + (16 * w + g) * PX_STR + t;
        #pragma unroll
        for (int ks = 0; ks < 16; ks++) {
            qa[ks][0] = __float_as_uint(ab[ks * 8]);
            qa[ks][1] = __float_as_uint(ab[8 * PX_STR + ks * 8]);
            qa[ks][2] = __float_as_uint(ab[ks * 8 + 4]);
            qa[ks][3] = __float_as_uint(ab[8 * PX_STR + ks * 8 + 4]);
        }
    }

    float acc[16][4];
    #pragma unroll
    for (int nb = 0; nb < 16; nb++)
        #pragma unroll
        for (int e = 0; e < 4; e++) acc[nb][e] = 0.f;

    const float* bb = Ws + g * PW_STR + t;
    #pragma unroll
    for (int ks = 0; ks < 16; ks++) {
        #pragma unroll
        for (int nb = 0; nb < 16; nb++) {
            uint32_t b0 = __float_as_uint(bb[nb * 8 * PW_STR + ks * 8]);
            uint32_t b1 = __float_as_uint(bb[nb * 8 * PW_STR + ks * 8 + 4]);
            mma8(acc[nb], qa[ks], b0, b1);
        }
    }

    // epilogue: scatter to [b][h][s][d]
    int m = m0 + 16 * w + g;
    int b = m >> 11, s = m & 2047;
    int hh = n0 >> 7;
    #pragma unroll
    for (int nb = 0; nb < 16; nb++) {
        int d = nb * 8 + 2 * t;
        float* dst = O + ((size_t)((b * NHEAD + hh) * S_LEN + s) * DHEAD + d);
        *(float2*)dst = make_float2(acc[nb][0], acc[nb][1]);
        *(float2*)(dst + 8 * DHEAD) = make_float2(acc[nb][2], acc[nb][3]);
    }
}

// ---------------------------------------------------------------------------
// Windowed attention via tf32 mma. CTA = 128 queries x (head, batch).
// 8 warps x 16 rows. Key tiles of 64, double-buffered.
//   K smem: [key][d] stride 132  (QK B-frag bank = g*4+t, conflict-free)
//   V smem: [key][d] stride 136  (PV B-frag bank = t*8+g, conflict-free)
// ---------------------------------------------------------------------------
#define KSTR 132
#define VSTR 136
// smem float offsets
#define SKB0 0
#define SKB1 (64*KSTR)                    // 8448
#define SVB0 (2*64*KSTR)                  // 16896
#define SVB1 (2*64*KSTR + 64*VSTR)        // 25600
#define SQS  (2*64*KSTR + 2*64*VSTR)      // 34304
#define SEMB (SQS + 128*KSTR)             // 51200
#define STOT (SEMB + 512)                 // 51712 floats = 206848 B

__device__ __forceinline__ void ldtile64(const float* __restrict__ src, int row0,
                                         float4* regs, int tid) {
    int r = tid >> 2, c0 = (tid & 3) << 5;
    const float* p = src + (size_t)(row0 + r) * DHEAD + c0;
    #pragma unroll
    for (int i = 0; i < 8; i++) regs[i] = *(const float4*)(p + i * 4);
}
template<int STR>
__device__ __forceinline__ void sttile64(float* buf, const float4* regs, int tid) {
    int r = tid >> 2, c0 = (tid & 3) << 5;
    float* p = buf + r * STR + c0;
    #pragma unroll
    for (int i = 0; i < 8; i++) *(uint4*)(p + i * 4) = cvt4(regs[i]);
}

__device__ __forceinline__ float pcalc(float a, int d, const float* __restrict__ embS) {
    if (d < 0) return 0.f;                      // causal+rpe: -2e9 -> exp = 0
    unsigned u = (unsigned)(d - 1);
    float bias = (u < 511u) ? embS[u] : -1e9f;  // out of window / diagonal -> underflow
    return __expf(fmaf(a, QK_SCALE, bias));
}

__global__ __launch_bounds__(256, 1) void attn_mma(
    const float* __restrict__ emb, float* __restrict__ out)
{
    extern __shared__ float sm[];
    float* embS = sm + SEMB;

    int tid = threadIdx.x;
    int lane = tid & 31, w = tid >> 5, g = lane >> 2, t = lane & 3;
    int qs = blockIdx.x << 7, h = blockIdx.y, b = blockIdx.z;
    size_t ho = (size_t)(b * NHEAD + h) * S_LEN * DHEAD;
    const float* Qh = g_Qp + ho;
    const float* Kh = g_Kp + ho;
    const float* Vh = g_Vp + ho;

    for (int i = tid; i < 512; i += 256) embS[i] = emb[i];

    // stage Q tile (tf32, stride 132)
    {
        int r = tid >> 1, kc = (tid & 1) << 6;
        const float* src = Qh + (size_t)(qs + r) * DHEAD + kc;
        #pragma unroll
        for (int i = 0; i < 16; i++)
            *(uint4*)&sm[SQS + r * KSTR + kc + i * 4] = cvt4(*(const float4*)(src + i * 4));
    }
    __syncthreads();

    // Q A-frags, register resident for whole kernel
    uint32_t qa[16][4];
    {
        const float* ab = sm + SQS + (16 * w + g) * KSTR + t;
        #pragma unroll
        for (int ks = 0; ks < 16; ks++) {
            qa[ks][0] = __float_as_uint(ab[ks * 8]);
            qa[ks][1] = __float_as_uint(ab[8 * KSTR + ks * 8]);
            qa[ks][2] = __float_as_uint(ab[ks * 8 + 4]);
            qa[ks][3] = __float_as_uint(ab[8 * KSTR + ks * 8 + 4]);
        }
    }

    float oacc[16][4];
    #pragma unroll
    for (int nb = 0; nb < 16; nb++)
        #pragma unroll
        for (int e = 0; e < 4; e++) oacc[nb][e] = 0.f;
    float sum0 = 0.f, sum1 = 0.f;

    int kt_lo = (qs >= WIN) ? ((qs - WIN) >> 6) : 0;
    int kt_hi = (qs + 127) >> 6;
    int T = kt_hi - kt_lo + 1;

    // prologue: tile 0 -> buffer 0
    {
        float4 kr[8], vr[8];
        ldtile64(Kh, kt_lo << 6, kr, tid);
        ldtile64(Vh, kt_lo << 6, vr, tid);
        sttile64<KSTR>(sm + SKB0, kr, tid);
        sttile64<VSTR>(sm + SVB0, vr, tid);
    }
    __syncthreads();

    int r_lo = qs + 16 * w, r_hi = r_lo + 15;
    int r0 = r_lo + g;

    for (int i = 0; i < T; i++) {
        int ks0 = (kt_lo + i) << 6;
        const float* kb = sm + ((i & 1) ? SKB1 : SKB0);
        const float* vb = sm + ((i & 1) ? SVB1 : SVB0);
        float* kbn = sm + ((i & 1) ? SKB0 : SKB1);
        float* vbn = sm + ((i & 1) ? SVB0 : SVB1);
        bool hasnext = (i + 1 < T);
        int nk = (kt_lo + i + 1) << 6;
        bool active = (ks0 <= r_hi) && (ks0 + 63 >= r_lo - WIN);

        float4 kreg[8];
        if (hasnext) ldtile64(Kh, nk, kreg, tid);

        // --- QK: S[16x64] ---
        float acc[8][4];
        #pragma unroll
        for (int nb = 0; nb < 8; nb++)
            #pragma unroll
            for (int e = 0; e < 4; e++) acc[nb][e] = 0.f;
        if (active) {
            const float* bbq = kb + g * KSTR + t;
            #pragma unroll
            for (int ks = 0; ks < 16; ks++) {
                #pragma unroll
                for (int nb = 0; nb < 8; nb++) {
                    uint32_t b0 = __float_as_uint(bbq[nb * 8 * KSTR + ks * 8]);
                    uint32_t b1 = __float_as_uint(bbq[nb * 8 * KSTR + ks * 8 + 4]);
                    mma8(acc[nb], qa[ks], b0, b1);
                }
            }
        }

        if (hasnext) sttile64<KSTR>(kbn, kreg, tid);
        float4 vreg[8];
        if (hasnext) ldtile64(Vh, nk, vreg, tid);

        // --- softmax (in-register, no max subtraction) ---
        uint32_t pu[8][4];
        if (active) {
            #pragma unroll
            for (int nb = 0; nb < 8; nb++) {
                int j0 = ks0 + nb * 8 + 2 * t;
                int d00 = r0 - j0;
                float p00 = pcalc(acc[nb][0], d00,     embS);
                float p01 = pcalc(acc[nb][1], d00 - 1, embS);
                float p10 = pcalc(acc[nb][2], d00 + 8, embS);
                float p11 = pcalc(acc[nb][3], d00 + 7, embS);
                sum0 += p00 + p01;
                sum1 += p10 + p11;
                pu[nb][0] = tf32r(p00); pu[nb][1] = tf32r(p01);
                pu[nb][2] = tf32r(p10); pu[nb][3] = tf32r(p11);
            }

            // --- PV: O += P @ V ---
            int base = lane & ~3;
            int l0 = base + (t >> 1), l1 = l0 + 2;
            bool odd = (t & 1);
            const float* bbv = vb + t * VSTR + g;
            #pragma unroll
            for (int ks = 0; ks < 8; ks++) {
                uint32_t pa[4];
                uint32_t x0 = __shfl_sync(0xffffffffu, pu[ks][0], l0);
                uint32_t x1 = __shfl_sync(0xffffffffu, pu[ks][1], l0);
                pa[0] = odd ? x1 : x0;
                x0 = __shfl_sync(0xffffffffu, pu[ks][2], l0);
                x1 = __shfl_sync(0xffffffffu, pu[ks][3], l0);
                pa[1] = odd ? x1 : x0;
                x0 = __shfl_sync(0xffffffffu, pu[ks][0], l1);
                x1 = __shfl_sync(0xffffffffu, pu[ks][1], l1);
                pa[2] = odd ? x1 : x0;
                x0 = __shfl_sync(0xffffffffu, pu[ks][2], l1);
                x1 = __shfl_sync(0xffffffffu, pu[ks][3], l1);
                pa[3] = odd ? x1 : x0;
                #pragma unroll
                for (int nb = 0; nb < 16; nb++) {
                    uint32_t b0 = __float_as_uint(bbv[ks * 8 * VSTR + nb * 8]);
                    uint32_t b1 = __float_as_uint(bbv[ks * 8 * VSTR + 4 * VSTR + nb * 8]);
                    mma8(oacc[nb], pa, b0, b1);
                }
            }
        }

        if (hasnext) sttile64<VSTR>(vbn, vreg, tid);
        __syncthreads();
    }

    // row-sum reduce within quad
    sum0 += __shfl_xor_sync(0xffffffffu, sum0, 1);
    sum0 += __shfl_xor_sync(0xffffffffu, sum0, 2);
    sum1 += __shfl_xor_sync(0xffffffffu, sum1, 1);
    sum1 += __shfl_xor_sync(0xffffffffu, sum1, 2);
    float linv0 = 1.f / sum0, linv1 = 1.f / sum1;

    // epilogue: out[b][s][h*128+d]; row 0 (fully masked) = V[0]
    float* dst0 = out + ((size_t)(b * S_LEN + r0) * (NHEAD * DHEAD)) + h * DHEAD + 2 * t;
    #pragma unroll
    for (int nb = 0; nb < 16; nb++) {
        float2 v0;
        if (r0 == 0) v0 = *(const float2*)(Vh + nb * 8 + 2 * t);
        else         v0 = make_float2(oacc[nb][0] * linv0, oacc[nb][1] * linv0);
        *(float2*)(dst0 + nb * 8) = v0;
        *(float2*)(dst0 + 8 * (NHEAD * DHEAD) + nb * 8) =
            make_float2(oacc[nb][2] * linv1, oacc[nb][3] * linv1);
    }
}

extern "C" void kernel_launch(void* const* d_in, const int* in_sizes, int n_in,
                              void* d_out, int out_size)
{
    (void)in_sizes; (void)n_in; (void)out_size;
    const float* q   = (const float*)d_in[0];
    const float* k   = (const float*)d_in[1];
    const float* v   = (const float*)d_in[2];
    const float* Wq  = (const float*)d_in[3];
    const float* Wk  = (const float*)d_in[4];
    const float* Wv  = (const float*)d_in[5];
    const float* emb = (const float*)d_in[6];
    float* out = (float*)d_out;

    cudaFuncSetAttribute(proj_mma, cudaFuncAttributeMaxDynamicSharedMemorySize, 135168);
    cudaFuncSetAttribute(attn_mma, cudaFuncAttributeMaxDynamicSharedMemorySize, STOT * 4);

    proj_mma<<<dim3(32, 8, 3), 256, 135168>>>(q, k, v, Wq, Wk, Wv);
    attn_mma<<<dim3(16, NHEAD, NB), 256, STOT * 4>>>(emb, out);
}

// round 9
// speedup vs baseline: 2.4564x; 1.1029x over previous
#include <cuda_runtime.h>
#include <math.h>
#include <stdint.h>

#define S_LEN 2048
#define DHEAD 128
#define NHEAD 8
#define NB 2
#define WIN 511
#define QK_SCALE 0.08838834764831845f   // 1/sqrt(128)

// Projected Q/K/V scratch: [B][H][S][D] fp32 (static device arrays, no allocs)
__device__ float g_Qp[NB*NHEAD*S_LEN*DHEAD];
__device__ float g_Kp[NB*NHEAD*S_LEN*DHEAD];
__device__ float g_Vp[NB*NHEAD*S_LEN*DHEAD];

// ---------------------------------------------------------------------------
// helpers
// ---------------------------------------------------------------------------
__device__ __forceinline__ uint32_t tf32r(float x) {
    uint32_t r; asm("cvt.rn.tf32.f32 %0, %1;" : "=r"(r) : "f"(x)); return r;
}
__device__ __forceinline__ void mma8(float* c, const uint32_t* a, uint32_t b0, uint32_t b1) {
    asm("mma.sync.aligned.m16n8k8.row.col.f32.tf32.tf32.f32 "
        "{%0,%1,%2,%3}, {%4,%5,%6,%7}, {%8,%9}, {%0,%1,%2,%3};"
        : "+f"(c[0]), "+f"(c[1]), "+f"(c[2]), "+f"(c[3])
        : "r"(a[0]), "r"(a[1]), "r"(a[2]), "r"(a[3]), "r"(b0), "r"(b1));
}
__device__ __forceinline__ uint4 cvt4(float4 a) {
    return make_uint4(tf32r(a.x), tf32r(a.y), tf32r(a.z), tf32r(a.w));
}
__device__ __forceinline__ void cpasync16(uint32_t dst, const void* src) {
    asm volatile("cp.async.cg.shared.global [%0], [%1], 16;" :: "r"(dst), "l"(src));
}
#define CP_COMMIT() asm volatile("cp.async.commit_group;" ::: "memory")
#define CP_WAIT0()  asm volatile("cp.async.wait_group 0;"  ::: "memory")

// ---------------------------------------------------------------------------
// Projection GEMM via tf32 mma: out[b,h,s,d] = X[4096,128] @ W[128,1024]
// CTA tile 128(m) x 64(n), 256 threads (8 warps x 16 rows), 2 CTAs/SM.
// ---------------------------------------------------------------------------
#define PX_STR 132
#define PW_STR 132

__global__ __launch_bounds__(256, 2) void proj_mma(
    const float* __restrict__ q, const float* __restrict__ k, const float* __restrict__ v,
    const float* __restrict__ Wq, const float* __restrict__ Wk, const float* __restrict__ Wv)
{
    extern __shared__ float sm[];
    float* Xs = sm;                    // [128][132]  row-major (m,k)
    float* Ws = sm + 128 * PX_STR;     // [64][132]   n-major   (n,k)

    const float *X, *W; float* O;
    if (blockIdx.z == 0)      { X = q; W = Wq; O = g_Qp; }
    else if (blockIdx.z == 1) { X = k; W = Wk; O = g_Kp; }
    else                      { X = v; W = Wv; O = g_Vp; }

    int m0 = blockIdx.x << 7;
    int n0 = blockIdx.y << 6;
    int tid = threadIdx.x;
    int lane = tid & 31, w = tid >> 5, g = lane >> 2, t = lane & 3;

    // stage X tile (cvt to tf32)
    {
        int r = tid >> 1, kc = (tid & 1) << 6;
        const float* src = X + (size_t)(m0 + r) * DHEAD + kc;
        #pragma unroll
        for (int i = 0; i < 16; i++)
            *(uint4*)&Xs[r * PX_STR + kc + i * 4] = cvt4(*(const float4*)(src + i * 4));
    }
    // stage W tile transposed to n-major (cvt to tf32)
    {
        int kk = tid >> 1, nc = (tid & 1) << 5;
        const float* src = W + (size_t)kk * 1024 + n0 + nc;
        #pragma unroll
        for (int i = 0; i < 8; i++) {
            float4 a = *(const float4*)(src + i * 4);
            float vv[4] = {a.x, a.y, a.z, a.w};
            #pragma unroll
            for (int e = 0; e < 4; e++)
                Ws[(nc + i * 4 + e) * PW_STR + kk] = __uint_as_float(tf32r(vv[e]));
        }
    }
    __syncthreads();

    // A frags (warp's 16 rows)
    uint32_t qa[16][4];
    {
        const float* ab = Xs + (16 * w + g) * PX_STR + t;
        #pragma unroll
        for (int ks = 0; ks < 16; ks++) {
            qa[ks][0] = __float_as_uint(ab[ks * 8]);
            qa[ks][1] = __float_as_uint(ab[8 * PX_STR + ks * 8]);
            qa[ks][2] = __float_as_uint(ab[ks * 8 + 4]);
            qa[ks][3] = __float_as_uint(ab[8 * PX_STR + ks * 8 + 4]);
        }
    }

    float acc[8][4];
    #pragma unroll
    for (int nb = 0; nb < 8; nb++)
        #pragma unroll
        for (int e = 0; e < 4; e++) acc[nb][e] = 0.f;

    const float* bb = Ws + g * PW_STR + t;
    #pragma unroll
    for (int ks = 0; ks < 16; ks++) {
        #pragma unroll
        for (int nb = 0; nb < 8; nb++) {
            uint32_t b0 = __float_as_uint(bb[nb * 8 * PW_STR + ks * 8]);
            uint32_t b1 = __float_as_uint(bb[nb * 8 * PW_STR + ks * 8 + 4]);
            mma8(acc[nb], qa[ks], b0, b1);
        }
    }

    // epilogue: scatter to [b][h][s][d]
    int m = m0 + 16 * w + g;
    int b = m >> 11, s = m & 2047;
    int hh = n0 >> 7, dbase = (n0 & 127);
    #pragma unroll
    for (int nb = 0; nb < 8; nb++) {
        int d = dbase + nb * 8 + 2 * t;
        float* dst = O + ((size_t)((b * NHEAD + hh) * S_LEN + s) * DHEAD + d);
        *(float2*)dst = make_float2(acc[nb][0], acc[nb][1]);
        *(float2*)(dst + 8 * DHEAD) = make_float2(acc[nb][2], acc[nb][3]);
    }
}

// ---------------------------------------------------------------------------
// Windowed attention via tf32 mma. CTA = 128 queries x (head, batch).
// 8 warps x 16 rows. Key tiles of 64, double-buffered via cp.async (raw fp32,
// hardware tf32-truncation in the mma).
//   K smem: [key][d] stride 132  (QK B-frag bank = g*4+t, conflict-free)
//   V smem: [key][d] stride 136  (PV B-frag bank = t*8+g, conflict-free)
//   P: per-warp [16][68] region carved out of the dead Q-staging smem.
// ---------------------------------------------------------------------------
#define KSTR 132
#define VSTR 136
#define PSTR 68
// smem float offsets
#define SKB0 0
#define SKB1 (64*KSTR)                    // 8448
#define SVB0 (2*64*KSTR)                  // 16896
#define SVB1 (2*64*KSTR + 64*VSTR)        // 25600
#define SQS  (2*64*KSTR + 2*64*VSTR)      // 34304  (Q staging, later P buffers)
#define SEMB (SQS + 128*KSTR)             // 51200
#define STOT (SEMB + 512)                 // 51712 floats = 206848 B

__device__ __forceinline__ void cp_kv(const float* __restrict__ Kh,
                                      const float* __restrict__ Vh, int row0,
                                      uint32_t kdst, uint32_t vdst, int tid) {
    int r = tid >> 2, c0 = (tid & 3) << 5;
    const float* ks = Kh + (size_t)(row0 + r) * DHEAD + c0;
    const float* vs = Vh + (size_t)(row0 + r) * DHEAD + c0;
    uint32_t kd = kdst + (uint32_t)(r * KSTR + c0) * 4u;
    uint32_t vd = vdst + (uint32_t)(r * VSTR + c0) * 4u;
    #pragma unroll
    for (int i = 0; i < 8; i++) {
        cpasync16(kd + i * 16, ks + i * 4);
        cpasync16(vd + i * 16, vs + i * 4);
    }
}

__device__ __forceinline__ float pcalc(float a, int d, const float* __restrict__ embS) {
    if (d < 0) return 0.f;                      // causal+rpe: -2e9 -> exp = 0
    unsigned u = (unsigned)(d - 1);
    float bias = (u < 511u) ? embS[u] : -1e9f;  // out of window / diagonal -> underflow
    return __expf(fmaf(a, QK_SCALE, bias));
}

__global__ __launch_bounds__(256, 1) void attn_mma(
    const float* __restrict__ emb, float* __restrict__ out)
{
    extern __shared__ float sm[];
    float* embS = sm + SEMB;
    uint32_t smb = (uint32_t)__cvta_generic_to_shared(sm);

    int tid = threadIdx.x;
    int lane = tid & 31, w = tid >> 5, g = lane >> 2, t = lane & 3;
    int qs = blockIdx.x << 7, h = blockIdx.y, b = blockIdx.z;
    size_t ho = (size_t)(b * NHEAD + h) * S_LEN * DHEAD;
    const float* Qh = g_Qp + ho;
    const float* Kh = g_Kp + ho;
    const float* Vh = g_Vp + ho;

    int kt_lo = (qs >= WIN) ? ((qs - WIN) >> 6) : 0;
    int kt_hi = (qs + 127) >> 6;
    int T = kt_hi - kt_lo + 1;

    // prefetch tile 0 into buffer 0 (overlaps Q staging below)
    cp_kv(Kh, Vh, kt_lo << 6, smb + SKB0 * 4, smb + SVB0 * 4, tid);
    CP_COMMIT();

    for (int i = tid; i < 512; i += 256) embS[i] = emb[i];

    // stage Q tile (tf32 RN, stride 132)
    {
        int r = tid >> 1, kc = (tid & 1) << 6;
        const float* src = Qh + (size_t)(qs + r) * DHEAD + kc;
        #pragma unroll
        for (int i = 0; i < 16; i++)
            *(uint4*)&sm[SQS + r * KSTR + kc + i * 4] = cvt4(*(const float4*)(src + i * 4));
    }
    __syncthreads();

    // Q A-frags, register resident for whole kernel
    uint32_t qa[16][4];
    {
        const float* ab = sm + SQS + (16 * w + g) * KSTR + t;
        #pragma unroll
        for (int ks = 0; ks < 16; ks++) {
            qa[ks][0] = __float_as_uint(ab[ks * 8]);
            qa[ks][1] = __float_as_uint(ab[8 * KSTR + ks * 8]);
            qa[ks][2] = __float_as_uint(ab[ks * 8 + 4]);
            qa[ks][3] = __float_as_uint(ab[8 * KSTR + ks * 8 + 4]);
        }
    }
    CP_WAIT0();
    __syncthreads();   // buf0 ready; all qa frags loaded -> Q region reusable as P

    float* Ps = sm + SQS + w * (16 * PSTR);   // per-warp P buffer [16][68]

    float oacc[16][4];
    #pragma unroll
    for (int nb = 0; nb < 16; nb++)
        #pragma unroll
        for (int e = 0; e < 4; e++) oacc[nb][e] = 0.f;
    float sum0 = 0.f, sum1 = 0.f;

    int r_lo = qs + 16 * w, r_hi = r_lo + 15;
    int r0 = r_lo + g;

    for (int i = 0; i < T; i++) {
        int ks0 = (kt_lo + i) << 6;
        const float* kb = sm + ((i & 1) ? SKB1 : SKB0);
        const float* vb = sm + ((i & 1) ? SVB1 : SVB0);
        bool hasnext = (i + 1 < T);
        bool active = (ks0 <= r_hi) && (ks0 + 63 >= r_lo - WIN);

        if (hasnext) {
            cp_kv(Kh, Vh, (kt_lo + i + 1) << 6,
                  smb + 4u * ((i & 1) ? SKB0 : SKB1),
                  smb + 4u * ((i & 1) ? SVB0 : SVB1), tid);
            CP_COMMIT();
        }

        if (active) {
            // --- QK: S[16x64] ---
            float acc[8][4];
            #pragma unroll
            for (int nb = 0; nb < 8; nb++)
                #pragma unroll
                for (int e = 0; e < 4; e++) acc[nb][e] = 0.f;
            const float* bbq = kb + g * KSTR + t;
            #pragma unroll
            for (int ks = 0; ks < 16; ks++) {
                #pragma unroll
                for (int nb = 0; nb < 8; nb++) {
                    uint32_t b0 = __float_as_uint(bbq[nb * 8 * KSTR + ks * 8]);
                    uint32_t b1 = __float_as_uint(bbq[nb * 8 * KSTR + ks * 8 + 4]);
                    mma8(acc[nb], qa[ks], b0, b1);
                }
            }

            // --- softmax (in-register, no max subtraction) + P store ---
            #pragma unroll
            for (int nb = 0; nb < 8; nb++) {
                int j0 = ks0 + nb * 8 + 2 * t;
                int d00 = r0 - j0;
                float p00 = pcalc(acc[nb][0], d00,     embS);
                float p01 = pcalc(acc[nb][1], d00 - 1, embS);
                float p10 = pcalc(acc[nb][2], d00 + 8, embS);
                float p11 = pcalc(acc[nb][3], d00 + 7, embS);
                sum0 += p00 + p01;
                sum1 += p10 + p11;
                *(uint2*)&Ps[g * PSTR + nb * 8 + 2 * t] =
                    make_uint2(tf32r(p00), tf32r(p01));
                *(uint2*)&Ps[(g + 8) * PSTR + nb * 8 + 2 * t] =
                    make_uint2(tf32r(p10), tf32r(p11));
            }
            __syncwarp();

            // --- PV: O += P @ V (A-frags from per-warp P smem) ---
            const float* bbv = vb + t * VSTR + g;
            #pragma unroll
            for (int ks = 0; ks < 8; ks++) {
                uint32_t pa[4];
                pa[0] = __float_as_uint(Ps[g * PSTR + ks * 8 + t]);
                pa[1] = __float_as_uint(Ps[(g + 8) * PSTR + ks * 8 + t]);
                pa[2] = __float_as_uint(Ps[g * PSTR + ks * 8 + t + 4]);
                pa[3] = __float_as_uint(Ps[(g + 8) * PSTR + ks * 8 + t + 4]);
                #pragma unroll
                for (int nb = 0; nb < 16; nb++) {
                    uint32_t b0 = __float_as_uint(bbv[ks * 8 * VSTR + nb * 8]);
                    uint32_t b1 = __float_as_uint(bbv[ks * 8 * VSTR + 4 * VSTR + nb * 8]);
                    mma8(oacc[nb], pa, b0, b1);
                }
            }
        }

        if (hasnext) CP_WAIT0();
        __syncthreads();
    }

    // row-sum reduce within quad
    sum0 += __shfl_xor_sync(0xffffffffu, sum0, 1);
    sum0 += __shfl_xor_sync(0xffffffffu, sum0, 2);
    sum1 += __shfl_xor_sync(0xffffffffu, sum1, 1);
    sum1 += __shfl_xor_sync(0xffffffffu, sum1, 2);
    float linv0 = 1.f / sum0, linv1 = 1.f / sum1;

    // epilogue: out[b][s][h*128+d]; row 0 (fully masked) = V[0]
    float* dst0 = out + ((size_t)(b * S_LEN + r0) * (NHEAD * DHEAD)) + h * DHEAD + 2 * t;
    #pragma unroll
    for (int nb = 0; nb < 16; nb++) {
        float2 v0;
        if (r0 == 0) v0 = *(const float2*)(Vh + nb * 8 + 2 * t);
        else         v0 = make_float2(oacc[nb][0] * linv0, oacc[nb][1] * linv0);
        *(float2*)(dst0 + nb * 8) = v0;
        *(float2*)(dst0 + 8 * (NHEAD * DHEAD) + nb * 8) =
            make_float2(oacc[nb][2] * linv1, oacc[nb][3] * linv1);
    }
}

extern "C" void kernel_launch(void* const* d_in, const int* in_sizes, int n_in,
                              void* d_out, int out_size)
{
    (void)in_sizes; (void)n_in; (void)out_size;
    const float* q   = (const float*)d_in[0];
    const float* k   = (const float*)d_in[1];
    const float* v   = (const float*)d_in[2];
    const float* Wq  = (const float*)d_in[3];
    const float* Wk  = (const float*)d_in[4];
    const float* Wv  = (const float*)d_in[5];
    const float* emb = (const float*)d_in[6];
    float* out = (float*)d_out;

    cudaFuncSetAttribute(proj_mma, cudaFuncAttributeMaxDynamicSharedMemorySize, 101376);
    cudaFuncSetAttribute(attn_mma, cudaFuncAttributeMaxDynamicSharedMemorySize, STOT * 4);

    proj_mma<<<dim3(32, 16, 3), 256, 101376>>>(q, k, v, Wq, Wk, Wv);
    attn_mma<<<dim3(16, NHEAD, NB), 256, STOT * 4>>>(emb, out);
}

// round 10
// speedup vs baseline: 2.8969x; 1.1793x over previous
#include <cuda_runtime.h>
#include <math.h>
#include <stdint.h>

#define S_LEN 2048
#define DHEAD 128
#define NHEAD 8
#define NB 2
#define WIN 511
#define QK_SCALE 0.08838834764831845f   // 1/sqrt(128)

// Projected Q/K/V scratch: [B][H][S][D] fp32. Q,K stored with d permuted
// within each 8-block: d -> (d&~7)|((d&3)<<1)|((d>>2)&1). V natural order.
__device__ float g_Qp[NB*NHEAD*S_LEN*DHEAD];
__device__ float g_Kp[NB*NHEAD*S_LEN*DHEAD];
__device__ float g_Vp[NB*NHEAD*S_LEN*DHEAD];

// ---------------------------------------------------------------------------
// helpers
// ---------------------------------------------------------------------------
__device__ __forceinline__ uint32_t tf32r(float x) {
    uint32_t r; asm("cvt.rn.tf32.f32 %0, %1;" : "=r"(r) : "f"(x)); return r;
}
__device__ __forceinline__ void mma8(float* c, const uint32_t* a, uint32_t b0, uint32_t b1) {
    asm("mma.sync.aligned.m16n8k8.row.col.f32.tf32.tf32.f32 "
        "{%0,%1,%2,%3}, {%4,%5,%6,%7}, {%8,%9}, {%0,%1,%2,%3};"
        : "+f"(c[0]), "+f"(c[1]), "+f"(c[2]), "+f"(c[3])
        : "r"(a[0]), "r"(a[1]), "r"(a[2]), "r"(a[3]), "r"(b0), "r"(b1));
}
__device__ __forceinline__ uint4 cvt4(float4 a) {
    return make_uint4(tf32r(a.x), tf32r(a.y), tf32r(a.z), tf32r(a.w));
}
__device__ __forceinline__ void cpasync16(uint32_t dst, const void* src) {
    asm volatile("cp.async.cg.shared.global [%0], [%1], 16;" :: "r"(dst), "l"(src));
}
#define CP_COMMIT() asm volatile("cp.async.commit_group;" ::: "memory")
#define CP_WAIT0()  asm volatile("cp.async.wait_group 0;"  ::: "memory")
__device__ __forceinline__ int permd(int d) {
    return (d & ~7) | ((d & 3) << 1) | ((d >> 2) & 1);
}

// ---------------------------------------------------------------------------
// Projection GEMM via tf32 mma: out[b,h,s,d] = X[4096,128] @ W[128,1024]
// CTA tile 128(m) x 128(n = one head), 256 threads (8 warps x 16 rows).
// W staged n-major with PERMUTED k-slots -> B-frags are single LDS.64.
// Q,K outputs stored with permuted d (exact reordering).
// ---------------------------------------------------------------------------
#define PX_STR 132
#define PW_STR 136

__global__ __launch_bounds__(256, 1) void proj_mma(
    const float* __restrict__ q, const float* __restrict__ k, const float* __restrict__ v,
    const float* __restrict__ Wq, const float* __restrict__ Wk, const float* __restrict__ Wv)
{
    extern __shared__ float sm[];
    float* Xs = sm;                    // [128][132]  row-major (m,k), natural k
    float* Ws = sm + 128 * PX_STR;     // [128][136]  n-major, k-slots permuted

    const float *X, *W; float* O; bool perm;
    if (blockIdx.z == 0)      { X = q; W = Wq; O = g_Qp; perm = true;  }
    else if (blockIdx.z == 1) { X = k; W = Wk; O = g_Kp; perm = true;  }
    else                      { X = v; W = Wv; O = g_Vp; perm = false; }

    int m0 = blockIdx.x << 7;
    int n0 = blockIdx.y << 7;          // == head * 128
    int tid = threadIdx.x;
    int lane = tid & 31, w = tid >> 5, g = lane >> 2, t = lane & 3;

    // stage X tile (cvt to tf32, natural k)
    {
        int r = tid >> 1, kc = (tid & 1) << 6;
        const float* src = X + (size_t)(m0 + r) * DHEAD + kc;
        #pragma unroll
        for (int i = 0; i < 16; i++)
            *(uint4*)&Xs[r * PX_STR + kc + i * 4] = cvt4(*(const float4*)(src + i * 4));
    }
    // stage W transposed to n-major with permuted k slot
    {
        int kk = tid >> 1, nc = (tid & 1) << 6;
        int kp = permd(kk);
        const float* src = W + (size_t)kk * 1024 + n0 + nc;
        #pragma unroll
        for (int i = 0; i < 16; i++) {
            float4 a = *(const float4*)(src + i * 4);
            float vv[4] = {a.x, a.y, a.z, a.w};
            #pragma unroll
            for (int e = 0; e < 4; e++)
                Ws[(nc + i * 4 + e) * PW_STR + kp] = __uint_as_float(tf32r(vv[e]));
        }
    }
    __syncthreads();

    // A frags (warp's 16 rows)
    uint32_t qa[16][4];
    {
        const float* ab = Xs + (16 * w + g) * PX_STR + t;
        #pragma unroll
        for (int ks = 0; ks < 16; ks++) {
            qa[ks][0] = __float_as_uint(ab[ks * 8]);
            qa[ks][1] = __float_as_uint(ab[8 * PX_STR + ks * 8]);
            qa[ks][2] = __float_as_uint(ab[ks * 8 + 4]);
            qa[ks][3] = __float_as_uint(ab[8 * PX_STR + ks * 8 + 4]);
        }
    }

    float acc[16][4];
    #pragma unroll
    for (int nb = 0; nb < 16; nb++)
        #pragma unroll
        for (int e = 0; e < 4; e++) acc[nb][e] = 0.f;

    #pragma unroll
    for (int ks = 0; ks < 16; ks++) {
        #pragma unroll
        for (int nb = 0; nb < 16; nb++) {
            uint2 bu = *(const uint2*)&Ws[(nb * 8 + g) * PW_STR + ks * 8 + 2 * t];
            mma8(acc[nb], qa[ks], bu.x, bu.y);
        }
    }

    // epilogue: scatter to [b][h][s][d] (Q,K with permuted d)
    int m = m0 + 16 * w + g;
    int b = m >> 11, s = m & 2047;
    int hh = n0 >> 7;
    float* dst = O + ((size_t)((b * NHEAD + hh) * S_LEN + s) * DHEAD);
    if (perm) {
        #pragma unroll
        for (int nb = 0; nb < 16; nb++) {
            int d0 = nb * 8 + 2 * t, d1 = d0 + 1;
            int p0 = permd(d0), p1 = permd(d1);
            dst[p0] = acc[nb][0];
            dst[p1] = acc[nb][1];
            dst[8 * DHEAD + p0] = acc[nb][2];
            dst[8 * DHEAD + p1] = acc[nb][3];
        }
    } else {
        #pragma unroll
        for (int nb = 0; nb < 16; nb++) {
            int d = nb * 8 + 2 * t;
            *(float2*)(dst + d) = make_float2(acc[nb][0], acc[nb][1]);
            *(float2*)(dst + 8 * DHEAD + d) = make_float2(acc[nb][2], acc[nb][3]);
        }
    }
}

// ---------------------------------------------------------------------------
// Windowed attention via tf32 mma. CTA = 128 queries x (head, batch),
// 512 threads = 16 warps = 8 warp-PAIRS; pair p owns query rows 16p..16p+15.
//   even warp of pair: QK keys 0-31,  PV d 0-63
//   odd  warp of pair: QK keys 32-63, PV d 64-127
// Key tiles of 64, double-buffered cp.async. Q/K d-permuted -> LDS.64 frags.
// ---------------------------------------------------------------------------
#define KSTR 136
#define VSTR 136
#define PSTR 68
// smem float offsets
#define SKB0 0
#define SKB1 (64*KSTR)                    // 8704
#define SVB0 (2*64*KSTR)                  // 17408
#define SVB1 (2*64*KSTR + 64*VSTR)        // 26112
#define SQS  (2*64*KSTR + 2*64*VSTR)      // 34816  Q staging; P pair bufs after qa load
#define SEMB (SQS + 128*KSTR)             // 52224
#define SLS  (SEMB + 512)                 // 52736  row-sum exchange [8][2][16]
#define STOT (SLS + 256)                  // 52992 floats = 211968 B

__device__ __forceinline__ void cp_kv512(const float* __restrict__ Kh,
                                         const float* __restrict__ Vh, int row0,
                                         uint32_t kdst, uint32_t vdst, int tid) {
    int r = tid >> 3, c0 = (tid & 7) << 4;
    const float* ks = Kh + (size_t)(row0 + r) * DHEAD + c0;
    const float* vs = Vh + (size_t)(row0 + r) * DHEAD + c0;
    uint32_t kd = kdst + (uint32_t)(r * KSTR + c0) * 4u;
    uint32_t vd = vdst + (uint32_t)(r * VSTR + c0) * 4u;
    #pragma unroll
    for (int i = 0; i < 4; i++) {
        cpasync16(kd + i * 16, ks + i * 4);
        cpasync16(vd + i * 16, vs + i * 4);
    }
}

__device__ __forceinline__ float pcalc(float a, int d, const float* __restrict__ embS) {
    if (d < 0) return 0.f;                      // causal+rpe: -2e9 -> exp = 0
    unsigned u = (unsigned)(d - 1);
    float bias = (u < 511u) ? embS[u] : -1e9f;  // out of window / diagonal -> underflow
    return __expf(fmaf(a, QK_SCALE, bias));
}

__global__ __launch_bounds__(512, 1) void attn_mma(
    const float* __restrict__ emb, float* __restrict__ out)
{
    extern __shared__ float sm[];
    float* embS = sm + SEMB;
    uint32_t smb = (uint32_t)__cvta_generic_to_shared(sm);

    int tid = threadIdx.x;
    int lane = tid & 31, w = tid >> 5, g = lane >> 2, t = lane & 3;
    int p = w >> 1, half = w & 1;
    int qs = blockIdx.x << 7, h = blockIdx.y, b = blockIdx.z;
    size_t ho = (size_t)(b * NHEAD + h) * S_LEN * DHEAD;
    const float* Qh = g_Qp + ho;
    const float* Kh = g_Kp + ho;
    const float* Vh = g_Vp + ho;

    int kt_lo = (qs >= WIN) ? ((qs - WIN) >> 6) : 0;
    int kt_hi = (qs + 127) >> 6;
    int T = kt_hi - kt_lo + 1;

    // prefetch tile 0 into buffer 0
    cp_kv512(Kh, Vh, kt_lo << 6, smb + SKB0 * 4, smb + SVB0 * 4, tid);
    CP_COMMIT();

    for (int i = tid; i < 512; i += 512) embS[i] = emb[i];

    // stage Q tile (tf32 RN; source already d-permuted)
    {
        int r = tid >> 2, kc = (tid & 3) << 5;
        const float* src = Qh + (size_t)(qs + r) * DHEAD + kc;
        #pragma unroll
        for (int i = 0; i < 8; i++)
            *(uint4*)&sm[SQS + r * KSTR + kc + i * 4] = cvt4(*(const float4*)(src + i * 4));
    }
    __syncthreads();

    // Q A-frags, persistent (LDS.64 on permuted pairs)
    uint32_t qa[16][4];
    {
        const float* ab = sm + SQS + (16 * p + g) * KSTR;
        #pragma unroll
        for (int ks = 0; ks < 16; ks++) {
            uint2 u0 = *(const uint2*)&ab[ks * 8 + 2 * t];
            uint2 u1 = *(const uint2*)&ab[8 * KSTR + ks * 8 + 2 * t];
            qa[ks][0] = u0.x; qa[ks][1] = u1.x; qa[ks][2] = u0.y; qa[ks][3] = u1.y;
        }
    }
    CP_WAIT0();
    __syncthreads();   // buf0 ready; all qa loaded -> Q region reusable as P

    float* Ps = sm + SQS + p * (16 * PSTR);   // per-PAIR P buffer [16][68]

    float oacc[8][4];
    #pragma unroll
    for (int nb = 0; nb < 8; nb++)
        #pragma unroll
        for (int e = 0; e < 4; e++) oacc[nb][e] = 0.f;
    float sum0 = 0.f, sum1 = 0.f;

    int r_lo = qs + 16 * p, r_hi = r_lo + 15;
    int r0 = r_lo + g;
    int nbq = half << 2;     // QK key-block offset (nb 0-3 / 4-7)
    int dvo = half << 6;     // PV d offset (0 / 64)

    for (int i = 0; i < T; i++) {
        int ks0 = (kt_lo + i) << 6;
        const float* kb = sm + ((i & 1) ? SKB1 : SKB0);
        const float* vb = sm + ((i & 1) ? SVB1 : SVB0);
        bool hasnext = (i + 1 < T);
        bool active = (ks0 <= r_hi) && (ks0 + 63 >= r_lo - WIN);

        if (hasnext) {
            cp_kv512(Kh, Vh, (kt_lo + i + 1) << 6,
                     smb + 4u * ((i & 1) ? SKB0 : SKB1),
                     smb + 4u * ((i & 1) ? SVB0 : SVB1), tid);
            CP_COMMIT();
        }

        if (active) {
            // --- QK: S[16 x 32] (this warp's key half) ---
            float acc[4][4];
            #pragma unroll
            for (int nb = 0; nb < 4; nb++)
                #pragma unroll
                for (int e = 0; e < 4; e++) acc[nb][e] = 0.f;
            #pragma unroll
            for (int ks = 0; ks < 16; ks++) {
                #pragma unroll
                for (int nb = 0; nb < 4; nb++) {
                    uint2 bu = *(const uint2*)&kb[((nbq + nb) * 8 + g) * KSTR + ks * 8 + 2 * t];
                    mma8(acc[nb], qa[ks], bu.x, bu.y);
                }
            }

            // --- softmax (no max subtraction) + P store into pair buffer ---
            #pragma unroll
            for (int nb = 0; nb < 4; nb++) {
                int j0 = ks0 + (nbq + nb) * 8 + 2 * t;
                int d00 = r0 - j0;
                float p00 = pcalc(acc[nb][0], d00,     embS);
                float p01 = pcalc(acc[nb][1], d00 - 1, embS);
                float p10 = pcalc(acc[nb][2], d00 + 8, embS);
                float p11 = pcalc(acc[nb][3], d00 + 7, embS);
                sum0 += p00 + p01;
                sum1 += p10 + p11;
                int c = (nbq + nb) * 8 + 2 * t;
                *(uint2*)&Ps[g * PSTR + c] = make_uint2(tf32r(p00), tf32r(p01));
                *(uint2*)&Ps[(g + 8) * PSTR + c] = make_uint2(tf32r(p10), tf32r(p11));
            }
            asm volatile("bar.sync %0, %1;" :: "r"(p + 1), "r"(64) : "memory");

            // --- PV: O[16 x 64] (this warp's d half) over all 64 keys ---
            #pragma unroll
            for (int ks = 0; ks < 8; ks++) {
                uint32_t pa[4];
                pa[0] = __float_as_uint(Ps[g * PSTR + ks * 8 + t]);
                pa[1] = __float_as_uint(Ps[(g + 8) * PSTR + ks * 8 + t]);
                pa[2] = __float_as_uint(Ps[g * PSTR + ks * 8 + t + 4]);
                pa[3] = __float_as_uint(Ps[(g + 8) * PSTR + ks * 8 + t + 4]);
                const float* bv = vb + (ks * 8 + t) * VSTR + dvo + g;
                #pragma unroll
                for (int nb = 0; nb < 8; nb++) {
                    uint32_t b0 = __float_as_uint(bv[nb * 8]);
                    uint32_t b1 = __float_as_uint(bv[4 * VSTR + nb * 8]);
                    mma8(oacc[nb], pa, b0, b1);
                }
            }
        }

        if (hasnext) CP_WAIT0();
        __syncthreads();   // K/V buffer swap + P overwrite hazard
    }

    // row sums: quad-reduce then combine the two key-halves via smem
    sum0 += __shfl_xor_sync(0xffffffffu, sum0, 1);
    sum0 += __shfl_xor_sync(0xffffffffu, sum0, 2);
    sum1 += __shfl_xor_sync(0xffffffffu, sum1, 1);
    sum1 += __shfl_xor_sync(0xffffffffu, sum1, 2);
    float* ls = sm + SLS;
    if (t == 0) {
        ls[(p * 2 + half) * 16 + g] = sum0;
        ls[(p * 2 + half) * 16 + g + 8] = sum1;
    }
    __syncthreads();
    float linv0 = 1.f / (ls[p * 32 + g] + ls[p * 32 + 16 + g]);
    float linv1 = 1.f / (ls[p * 32 + g + 8] + ls[p * 32 + 16 + g + 8]);

    // epilogue: out[b][s][h*128+d]; row 0 (fully masked) = V[0]
    float* dst0 = out + ((size_t)(b * S_LEN + r0) * (NHEAD * DHEAD)) + h * DHEAD + dvo + 2 * t;
    #pragma unroll
    for (int nb = 0; nb < 8; nb++) {
        float2 v0;
        if (r0 == 0) v0 = make_float2(Vh[dvo + nb * 8 + 2 * t], Vh[dvo + nb * 8 + 2 * t + 1]);
        else         v0 = make_float2(oacc[nb][0] * linv0, oacc[nb][1] * linv0);
        *(float2*)(dst0 + nb * 8) = v0;
        *(float2*)(dst0 + 8 * (NHEAD * DHEAD) + nb * 8) =
            make_float2(oacc[nb][2] * linv1, oacc[nb][3] * linv1);
    }
}

extern "C" void kernel_launch(void* const* d_in, const int* in_sizes, int n_in,
                              void* d_out, int out_size)
{
    (void)in_sizes; (void)n_in; (void)out_size;
    const float* q   = (const float*)d_in[0];
    const float* k   = (const float*)d_in[1];
    const float* v   = (const float*)d_in[2];
    const float* Wq  = (const float*)d_in[3];
    const float* Wk  = (const float*)d_in[4];
    const float* Wv  = (const float*)d_in[5];
    const float* emb = (const float*)d_in[6];
    float* out = (float*)d_out;

    cudaFuncSetAttribute(proj_mma, cudaFuncAttributeMaxDynamicSharedMemorySize, 137216);
    cudaFuncSetAttribute(attn_mma, cudaFuncAttributeMaxDynamicSharedMemorySize, STOT * 4);

    proj_mma<<<dim3(32, 8, 3), 256, 137216>>>(q, k, v, Wq, Wk, Wv);
    attn_mma<<<dim3(16, NHEAD, NB), 512, STOT * 4>>>(emb, out);
}

// round 13
// speedup vs baseline: 2.9622x; 1.0225x over previous
#include <cuda_runtime.h>
#include <math.h>
#include <stdint.h>

#define S_LEN 2048
#define DHEAD 128
#define NHEAD 8
#define NB 2
#define WIN 511
#define QK_SCALE 0.08838834764831845f   // 1/sqrt(128)

// Projected Q/K/V scratch: [B][H][S][D] fp32. Q,K stored with d permuted
// within each 8-block: d -> (d&~7)|((d&3)<<1)|((d>>2)&1). V natural order.
__device__ float g_Qp[NB*NHEAD*S_LEN*DHEAD];
__device__ float g_Kp[NB*NHEAD*S_LEN*DHEAD];
__device__ float g_Vp[NB*NHEAD*S_LEN*DHEAD];

// ---------------------------------------------------------------------------
// helpers
// ---------------------------------------------------------------------------
__device__ __forceinline__ uint32_t tf32r(float x) {
    uint32_t r; asm("cvt.rn.tf32.f32 %0, %1;" : "=r"(r) : "f"(x)); return r;
}
__device__ __forceinline__ void mma8(float* c, const uint32_t* a, uint32_t b0, uint32_t b1) {
    asm("mma.sync.aligned.m16n8k8.row.col.f32.tf32.tf32.f32 "
        "{%0,%1,%2,%3}, {%4,%5,%6,%7}, {%8,%9}, {%0,%1,%2,%3};"
        : "+f"(c[0]), "+f"(c[1]), "+f"(c[2]), "+f"(c[3])
        : "r"(a[0]), "r"(a[1]), "r"(a[2]), "r"(a[3]), "r"(b0), "r"(b1));
}
__device__ __forceinline__ uint4 cvt4(float4 a) {
    return make_uint4(tf32r(a.x), tf32r(a.y), tf32r(a.z), tf32r(a.w));
}
__device__ __forceinline__ void cpasync16(uint32_t dst, const void* src) {
    asm volatile("cp.async.cg.shared.global [%0], [%1], 16;" :: "r"(dst), "l"(src));
}
#define CP_COMMIT() asm volatile("cp.async.commit_group;" ::: "memory")
#define CP_WAIT0()  asm volatile("cp.async.wait_group 0;"  ::: "memory")
__device__ __forceinline__ int permd(int d) {
    return (d & ~7) | ((d & 3) << 1) | ((d >> 2) & 1);
}

// ---------------------------------------------------------------------------
// Projection GEMM via tf32 mma: out[b,h,s,d] = X[4096,128] @ W[128,1024]
// CTA tile 128(m) x 128(n = one head), 512 threads = 16 warps = 8 pairs.
// Pair p owns rows 16p..16p+15; even/odd warp of pair owns n 0-63 / 64-127.
// X staged raw fp32 via cp.async (RN cvt at A-frag build). W staged n-major
// with PERMUTED k-slots -> B-frags are single LDS.64.
// ---------------------------------------------------------------------------
#define PX_STR 132
#define PW_STR 136

__global__ __launch_bounds__(512, 1) void proj_mma(
    const float* __restrict__ q, const float* __restrict__ k, const float* __restrict__ v,
    const float* __restrict__ Wq, const float* __restrict__ Wk, const float* __restrict__ Wv)
{
    extern __shared__ float sm[];
    float* Xs = sm;                    // [128][132]  row-major (m,k), raw fp32
    float* Ws = sm + 128 * PX_STR;     // [128][136]  n-major, k-slots permuted, tf32
    uint32_t smb = (uint32_t)__cvta_generic_to_shared(sm);

    const float *X, *W; float* O; bool perm;
    if (blockIdx.z == 0)      { X = q; W = Wq; O = g_Qp; perm = true;  }
    else if (blockIdx.z == 1) { X = k; W = Wk; O = g_Kp; perm = true;  }
    else                      { X = v; W = Wv; O = g_Vp; perm = false; }

    int m0 = blockIdx.x << 7;
    int n0 = blockIdx.y << 7;          // == head * 128
    int tid = threadIdx.x;
    int lane = tid & 31, w = tid >> 5, g = lane >> 2, t = lane & 3;
    int p = w >> 1, half = w & 1;

    // stage X tile via cp.async (raw fp32)
    {
        int r = tid >> 2, c0 = (tid & 3) << 5;
        const float* src = X + (size_t)(m0 + r) * DHEAD + c0;
        uint32_t dst = smb + (uint32_t)(r * PX_STR + c0) * 4u;
        #pragma unroll
        for (int i = 0; i < 8; i++) cpasync16(dst + i * 16, src + i * 4);
    }
    CP_COMMIT();

    // stage W transposed to n-major with permuted k slot (tf32 RN)
    {
        int kk = tid >> 2, nc = (tid & 3) << 5;
        int kp = permd(kk);
        const float* src = W + (size_t)kk * 1024 + n0 + nc;
        #pragma unroll
        for (int i = 0; i < 8; i++) {
            float4 a = *(const float4*)(src + i * 4);
            float vv[4] = {a.x, a.y, a.z, a.w};
            #pragma unroll
            for (int e = 0; e < 4; e++)
                Ws[(nc + i * 4 + e) * PW_STR + kp] = __uint_as_float(tf32r(vv[e]));
        }
    }
    CP_WAIT0();
    __syncthreads();

    // A frags (pair's 16 rows), cvt RN here (one-time)
    uint32_t qa[16][4];
    {
        const float* ab = Xs + (16 * p + g) * PX_STR + t;
        #pragma unroll
        for (int ks = 0; ks < 16; ks++) {
            qa[ks][0] = tf32r(ab[ks * 8]);
            qa[ks][1] = tf32r(ab[8 * PX_STR + ks * 8]);
            qa[ks][2] = tf32r(ab[ks * 8 + 4]);
            qa[ks][3] = tf32r(ab[8 * PX_STR + ks * 8 + 4]);
        }
    }

    float acc[8][4];
    #pragma unroll
    for (int nb = 0; nb < 8; nb++)
        #pragma unroll
        for (int e = 0; e < 4; e++) acc[nb][e] = 0.f;

    int nbo = half << 3;   // n-block offset (0 or 8)
    #pragma unroll
    for (int ks = 0; ks < 16; ks++) {
        #pragma unroll
        for (int nb = 0; nb < 8; nb++) {
            uint2 bu = *(const uint2*)&Ws[((nbo + nb) * 8 + g) * PW_STR + ks * 8 + 2 * t];
            mma8(acc[nb], qa[ks], bu.x, bu.y);
        }
    }

    // epilogue: scatter to [b][h][s][d] (Q,K with permuted d)
    int m = m0 + 16 * p + g;
    int b = m >> 11, s = m & 2047;
    int hh = n0 >> 7, dbase = half << 6;
    float* dst = O + ((size_t)((b * NHEAD + hh) * S_LEN + s) * DHEAD);
    if (perm) {
        #pragma unroll
        for (int nb = 0; nb < 8; nb++) {
            int d0 = dbase + nb * 8 + 2 * t, d1 = d0 + 1;
            int p0 = permd(d0), p1 = permd(d1);
            dst[p0] = acc[nb][0];
            dst[p1] = acc[nb][1];
            dst[8 * DHEAD + p0] = acc[nb][2];
            dst[8 * DHEAD + p1] = acc[nb][3];
        }
    } else {
        #pragma unroll
        for (int nb = 0; nb < 8; nb++) {
            int d = dbase + nb * 8 + 2 * t;
            *(float2*)(dst + d) = make_float2(acc[nb][0], acc[nb][1]);
            *(float2*)(dst + 8 * DHEAD + d) = make_float2(acc[nb][2], acc[nb][3]);
        }
    }
}

// ---------------------------------------------------------------------------
// Windowed attention via tf32 mma. CTA = 128 queries x (head, batch),
// 512 threads = 16 warps = 8 warp-PAIRS; pair p owns query rows 16p..16p+15.
//   even warp of pair: QK keys 0-31,  PV d 0-63
//   odd  warp of pair: QK keys 32-63, PV d 64-127
// Key tiles of 64, double-buffered cp.async. Q/K d-permuted -> LDS.64 frags.
// qt remapped heavy-first so the light (low-qt) CTAs fill the wave-2 tail.
// ---------------------------------------------------------------------------
#define KSTR 136
#define VSTR 136
#define PSTR 68
// smem float offsets
#define SKB0 0
#define SKB1 (64*KSTR)                    // 8704
#define SVB0 (2*64*KSTR)                  // 17408
#define SVB1 (2*64*KSTR + 64*VSTR)        // 26112
#define SQS  (2*64*KSTR + 2*64*VSTR)      // 34816  Q staging; P pair bufs after qa load
#define SEMB (SQS + 128*KSTR)             // 52224
#define SLS  (SEMB + 512)                 // 52736  row-sum exchange [8][2][16]
#define STOT (SLS + 256)                  // 52992 floats = 211968 B

__device__ __forceinline__ void cp_kv512(const float* __restrict__ Kh,
                                         const float* __restrict__ Vh, int row0,
                                         uint32_t kdst, uint32_t vdst, int tid) {
    int r = tid >> 3, c0 = (tid & 7) << 4;
    const float* ks = Kh + (size_t)(row0 + r) * DHEAD + c0;
    const float* vs = Vh + (size_t)(row0 + r) * DHEAD + c0;
    uint32_t kd = kdst + (uint32_t)(r * KSTR + c0) * 4u;
    uint32_t vd = vdst + (uint32_t)(r * VSTR + c0) * 4u;
    #pragma unroll
    for (int i = 0; i < 4; i++) {
        cpasync16(kd + i * 16, ks + i * 4);
        cpasync16(vd + i * 16, vs + i * 4);
    }
}

__device__ __forceinline__ float pcalc(float a, int d, const float* __restrict__ embS) {
    if (d < 0) return 0.f;                      // causal+rpe: -2e9 -> exp = 0
    unsigned u = (unsigned)(d - 1);
    float bias = (u < 511u) ? embS[u] : -1e9f;  // out of window / diagonal -> underflow
    return __expf(fmaf(a, QK_SCALE, bias));
}

__global__ __launch_bounds__(512, 1) void attn_mma(
    const float* __restrict__ emb, float* __restrict__ out)
{
    extern __shared__ float sm[];
    float* embS = sm + SEMB;
    uint32_t smb = (uint32_t)__cvta_generic_to_shared(sm);

    int tid = threadIdx.x;
    int lane = tid & 31, w = tid >> 5, g = lane >> 2, t = lane & 3;
    int p = w >> 1, half = w & 1;
    // heavy-first launch order: x=0..11 -> qt 4..15 (T=10), x=12..15 -> qt 0..3
    int qt = (blockIdx.x + 4) & 15;
    int qs = qt << 7, h = blockIdx.y, b = blockIdx.z;
    size_t ho = (size_t)(b * NHEAD + h) * S_LEN * DHEAD;
    const float* Qh = g_Qp + ho;
    const float* Kh = g_Kp + ho;
    const float* Vh = g_Vp + ho;

    int kt_lo = (qs >= WIN) ? ((qs - WIN) >> 6) : 0;
    int kt_hi = (qs + 127) >> 6;
    int T = kt_hi - kt_lo + 1;

    // prefetch tile 0 into buffer 0
    cp_kv512(Kh, Vh, kt_lo << 6, smb + SKB0 * 4, smb + SVB0 * 4, tid);
    CP_COMMIT();

    for (int i = tid; i < 512; i += 512) embS[i] = emb[i];

    // stage Q tile (tf32 RN; source already d-permuted)
    {
        int r = tid >> 2, kc = (tid & 3) << 5;
        const float* src = Qh + (size_t)(qs + r) * DHEAD + kc;
        #pragma unroll
        for (int i = 0; i < 8; i++)
            *(uint4*)&sm[SQS + r * KSTR + kc + i * 4] = cvt4(*(const float4*)(src + i * 4));
    }
    __syncthreads();

    // Q A-frags, persistent (LDS.64 on permuted pairs)
    uint32_t qa[16][4];
    {
        const float* ab = sm + SQS + (16 * p + g) * KSTR;
        #pragma unroll
        for (int ks = 0; ks < 16; ks++) {
            uint2 u0 = *(const uint2*)&ab[ks * 8 + 2 * t];
            uint2 u1 = *(const uint2*)&ab[8 * KSTR + ks * 8 + 2 * t];
            qa[ks][0] = u0.x; qa[ks][1] = u1.x; qa[ks][2] = u0.y; qa[ks][3] = u1.y;
        }
    }
    CP_WAIT0();
    __syncthreads();   // buf0 ready; all qa loaded -> Q region reusable as P

    float* Ps = sm + SQS + p * (16 * PSTR);   // per-PAIR P buffer [16][68]

    float oacc[8][4];
    #pragma unroll
    for (int nb = 0; nb < 8; nb++)
        #pragma unroll
        for (int e = 0; e < 4; e++) oacc[nb][e] = 0.f;
    float sum0 = 0.f, sum1 = 0.f;

    int r_lo = qs + 16 * p, r_hi = r_lo + 15;
    int r0 = r_lo + g;
    int nbq = half << 2;     // QK key-block offset (nb 0-3 / 4-7)
    int dvo = half << 6;     // PV d offset (0 / 64)

    for (int i = 0; i < T; i++) {
        int ks0 = (kt_lo + i) << 6;
        const float* kb = sm + ((i & 1) ? SKB1 : SKB0);
        const float* vb = sm + ((i & 1) ? SVB1 : SVB0);
        bool hasnext = (i + 1 < T);
        bool active = (ks0 <= r_hi) && (ks0 + 63 >= r_lo - WIN);

        if (hasnext) {
            cp_kv512(Kh, Vh, (kt_lo + i + 1) << 6,
                     smb + 4u * ((i & 1) ? SKB0 : SKB1),
                     smb + 4u * ((i & 1) ? SVB0 : SVB1), tid);
            CP_COMMIT();
        }

        if (active) {
            // --- QK: S[16 x 32] (this warp's key half) ---
            float acc[4][4];
            #pragma unroll
            for (int nb = 0; nb < 4; nb++)
                #pragma unroll
                for (int e = 0; e < 4; e++) acc[nb][e] = 0.f;
            #pragma unroll
            for (int ks = 0; ks < 16; ks++) {
                #pragma unroll
                for (int nb = 0; nb < 4; nb++) {
                    uint2 bu = *(const uint2*)&kb[((nbq + nb) * 8 + g) * KSTR + ks * 8 + 2 * t];
                    mma8(acc[nb], qa[ks], bu.x, bu.y);
                }
            }

            // --- softmax (no max subtraction) + P store into pair buffer ---
            #pragma unroll
            for (int nb = 0; nb < 4; nb++) {
                int j0 = ks0 + (nbq + nb) * 8 + 2 * t;
                int d00 = r0 - j0;
                float p00 = pcalc(acc[nb][0], d00,     embS);
                float p01 = pcalc(acc[nb][1], d00 - 1, embS);
                float p10 = pcalc(acc[nb][2], d00 + 8, embS);
                float p11 = pcalc(acc[nb][3], d00 + 7, embS);
                sum0 += p00 + p01;
                sum1 += p10 + p11;
                int c = (nbq + nb) * 8 + 2 * t;
                *(uint2*)&Ps[g * PSTR + c] = make_uint2(tf32r(p00), tf32r(p01));
                *(uint2*)&Ps[(g + 8) * PSTR + c] = make_uint2(tf32r(p10), tf32r(p11));
            }
            asm volatile("bar.sync %0, %1;" :: "r"(p + 1), "r"(64) : "memory");

            // --- PV: O[16 x 64] (this warp's d half) over all 64 keys ---
            #pragma unroll
            for (int ks = 0; ks < 8; ks++) {
                uint32_t pa[4];
                pa[0] = __float_as_uint(Ps[g * PSTR + ks * 8 + t]);
                pa[1] = __float_as_uint(Ps[(g + 8) * PSTR + ks * 8 + t]);
                pa[2] = __float_as_uint(Ps[g * PSTR + ks * 8 + t + 4]);
                pa[3] = __float_as_uint(Ps[(g + 8) * PSTR + ks * 8 + t + 4]);
                const float* bv = vb + (ks * 8 + t) * VSTR + dvo + g;
                #pragma unroll
                for (int nb = 0; nb < 8; nb++) {
                    uint32_t b0 = __float_as_uint(bv[nb * 8]);
                    uint32_t b1 = __float_as_uint(bv[4 * VSTR + nb * 8]);
                    mma8(oacc[nb], pa, b0, b1);
                }
            }
        }

        if (hasnext) CP_WAIT0();
        __syncthreads();   // K/V buffer swap + P overwrite hazard
    }

    // row sums: quad-reduce then combine the two key-halves via smem
    sum0 += __shfl_xor_sync(0xffffffffu, sum0, 1);
    sum0 += __shfl_xor_sync(0xffffffffu, sum0, 2);
    sum1 += __shfl_xor_sync(0xffffffffu, sum1, 1);
    sum1 += __shfl_xor_sync(0xffffffffu, sum1, 2);
    float* ls = sm + SLS;
    if (t == 0) {
        ls[(p * 2 + half) * 16 + g] = sum0;
        ls[(p * 2 + half) * 16 + g + 8] = sum1;
    }
    __syncthreads();
    float linv0 = 1.f / (ls[p * 32 + g] + ls[p * 32 + 16 + g]);
    float linv1 = 1.f / (ls[p * 32 + g + 8] + ls[p * 32 + 16 + g + 8]);

    // epilogue: out[b][s][h*128+d]; row 0 (fully masked) = V[0]
    float* dst0 = out + ((size_t)(b * S_LEN + r0) * (NHEAD * DHEAD)) + h * DHEAD + dvo + 2 * t;
    #pragma unroll
    for (int nb = 0; nb < 8; nb++) {
        float2 v0;
        if (r0 == 0) v0 = make_float2(Vh[dvo + nb * 8 + 2 * t], Vh[dvo + nb * 8 + 2 * t + 1]);
        else         v0 = make_float2(oacc[nb][0] * linv0, oacc[nb][1] * linv0);
        *(float2*)(dst0 + nb * 8) = v0;
        *(float2*)(dst0 + 8 * (NHEAD * DHEAD) + nb * 8) =
            make_float2(oacc[nb][2] * linv1, oacc[nb][3] * linv1);
    }
}

extern "C" void kernel_launch(void* const* d_in, const int* in_sizes, int n_in,
                              void* d_out, int out_size)
{
    (void)in_sizes; (void)n_in; (void)out_size;
    const float* q   = (const float*)d_in[0];
    const float* k   = (const float*)d_in[1];
    const float* v   = (const float*)d_in[2];
    const float* Wq  = (const float*)d_in[3];
    const float* Wk  = (const float*)d_in[4];
    const float* Wv  = (const float*)d_in[5];
    const float* emb = (const float*)d_in[6];
    float* out = (float*)d_out;

    cudaFuncSetAttribute(proj_mma, cudaFuncAttributeMaxDynamicSharedMemorySize, 137216);
    cudaFuncSetAttribute(attn_mma, cudaFuncAttributeMaxDynamicSharedMemorySize, STOT * 4);

    proj_mma<<<dim3(32, 8, 3), 512, 137216>>>(q, k, v, Wq, Wk, Wv);
    attn_mma<<<dim3(16, NHEAD, NB), 512, STOT * 4>>>(emb, out);
}

// round 15
// speedup vs baseline: 3.1831x; 1.0746x over previous
#include <cuda_runtime.h>
#include <math.h>
#include <stdint.h>

#define S_LEN 2048
#define DHEAD 128
#define NHEAD 8
#define NB 2
#define WIN 511
#define QK_SCALE 0.08838834764831845f   // 1/sqrt(128)
#define LOG2E 1.4426950408889634f
#define QK_SL2E (QK_SCALE * LOG2E)

// Projected Q/K/V scratch: [B][H][S][D] fp32. Q,K stored with d permuted
// within each 8-block: d -> (d&~7)|((d&3)<<1)|((d>>2)&1). V natural order.
__device__ float g_Qp[NB*NHEAD*S_LEN*DHEAD];
__device__ float g_Kp[NB*NHEAD*S_LEN*DHEAD];
__device__ float g_Vp[NB*NHEAD*S_LEN*DHEAD];

// ---------------------------------------------------------------------------
// helpers
// ---------------------------------------------------------------------------
__device__ __forceinline__ uint32_t tf32r(float x) {
    uint32_t r; asm("cvt.rn.tf32.f32 %0, %1;" : "=r"(r) : "f"(x)); return r;
}
__device__ __forceinline__ void mma8(float* c, const uint32_t* a, uint32_t b0, uint32_t b1) {
    asm("mma.sync.aligned.m16n8k8.row.col.f32.tf32.tf32.f32 "
        "{%0,%1,%2,%3}, {%4,%5,%6,%7}, {%8,%9}, {%0,%1,%2,%3};"
        : "+f"(c[0]), "+f"(c[1]), "+f"(c[2]), "+f"(c[3])
        : "r"(a[0]), "r"(a[1]), "r"(a[2]), "r"(a[3]), "r"(b0), "r"(b1));
}
__device__ __forceinline__ uint4 cvt4(float4 a) {
    return make_uint4(tf32r(a.x), tf32r(a.y), tf32r(a.z), tf32r(a.w));
}
__device__ __forceinline__ void cpasync16(uint32_t dst, const void* src) {
    asm volatile("cp.async.cg.shared.global [%0], [%1], 16;" :: "r"(dst), "l"(src));
}
#define CP_COMMIT() asm volatile("cp.async.commit_group;" ::: "memory")
#define CP_WAIT0()  asm volatile("cp.async.wait_group 0;"  ::: "memory")
__device__ __forceinline__ int permd(int d) {
    return (d & ~7) | ((d & 3) << 1) | ((d >> 2) & 1);
}

// ---------------------------------------------------------------------------
// Projection GEMM via tf32 mma: out[b,h,s,d] = X[4096,128] @ W[128,1024]
// CTA tile 128(m) x 128(n = one head), 512 threads = 16 warps = 8 pairs.
// X staged raw fp32 via coalesced cp.async (RN cvt at A-frag build).
// W staged n-major, permuted k-slots, ROW-SKEWED (+ (row>>2)*8) so both the
// transpose STS and the B-frag LDS.64 are bank-conflict-free.
// ---------------------------------------------------------------------------
#define PX_STR 132
#define PW_STR 136
#define WS_SIZE 17648   // 127*136 + 31*8 + 127 + 1

__global__ __launch_bounds__(512, 1) void proj_mma(
    const float* __restrict__ q, const float* __restrict__ k, const float* __restrict__ v,
    const float* __restrict__ Wq, const float* __restrict__ Wk, const float* __restrict__ Wv)
{
    extern __shared__ float sm[];
    float* Xs = sm;                    // [128][132]  row-major (m,k), raw fp32
    float* Ws = sm + 128 * PX_STR;     // skewed n-major, k-slots permuted, tf32
    uint32_t smb = (uint32_t)__cvta_generic_to_shared(sm);

    const float *X, *W; float* O; bool perm;
    if (blockIdx.z == 0)      { X = q; W = Wq; O = g_Qp; perm = true;  }
    else if (blockIdx.z == 1) { X = k; W = Wk; O = g_Kp; perm = true;  }
    else                      { X = v; W = Wv; O = g_Vp; perm = false; }

    int m0 = blockIdx.x << 7;
    int n0 = blockIdx.y << 7;          // == head * 128
    int tid = threadIdx.x;
    int lane = tid & 31, w = tid >> 5, g = lane >> 2, t = lane & 3;
    int p = w >> 1, half = w & 1;

    // stage X tile via coalesced cp.async (raw fp32): 2 passes of 64 rows
    {
        int r = tid >> 3, c0 = (tid & 7) << 4;
        #pragma unroll
        for (int hv = 0; hv < 2; hv++) {
            int rr = r + hv * 64;
            const float* src = X + (size_t)(m0 + rr) * DHEAD + c0;
            uint32_t dst = smb + (uint32_t)(rr * PX_STR + c0) * 4u;
            #pragma unroll
            for (int i = 0; i < 4; i++) cpasync16(dst + i * 16, src + i * 4);
        }
    }
    CP_COMMIT();

    // stage W transposed to skewed n-major with permuted k slot (tf32 RN)
    {
        int kk = tid >> 2, kp = permd(kk);
        const float* wsrc = W + (size_t)kk * 1024 + n0;
        #pragma unroll
        for (int j = 0; j < 8; j++) {
            int n = (tid & 3) * 4 + j * 16;
            float4 a = *(const float4*)(wsrc + n);
            float vv[4] = {a.x, a.y, a.z, a.w};
            float* wd = Ws + ((n >> 2) << 3) + kp;   // skew const over e (n mult of 4)
            #pragma unroll
            for (int e = 0; e < 4; e++)
                wd[(n + e) * PW_STR] = __uint_as_float(tf32r(vv[e]));
        }
    }
    CP_WAIT0();
    __syncthreads();

    // A frags (pair's 16 rows), cvt RN here (one-time)
    uint32_t qa[16][4];
    {
        const float* ab = Xs + (16 * p + g) * PX_STR + t;
        #pragma unroll
        for (int ks = 0; ks < 16; ks++) {
            qa[ks][0] = tf32r(ab[ks * 8]);
            qa[ks][1] = tf32r(ab[8 * PX_STR + ks * 8]);
            qa[ks][2] = tf32r(ab[ks * 8 + 4]);
            qa[ks][3] = tf32r(ab[8 * PX_STR + ks * 8 + 4]);
        }
    }

    float acc[8][4];
    #pragma unroll
    for (int nb = 0; nb < 8; nb++)
        #pragma unroll
        for (int e = 0; e < 4; e++) acc[nb][e] = 0.f;

    int nbo = half << 3;   // n-block offset (0 or 8)
    #pragma unroll
    for (int nb = 0; nb < 8; nb++) {
        int row = (nbo + nb) * 8 + g;
        const float* wrow = Ws + row * PW_STR + ((row >> 2) << 3) + 2 * t;
        #pragma unroll
        for (int ks = 0; ks < 16; ks++) {
            uint2 bu = *(const uint2*)&wrow[ks * 8];
            mma8(acc[nb], qa[ks], bu.x, bu.y);
        }
    }

    // epilogue: scatter to [b][h][s][d] (Q,K with permuted d)
    int m = m0 + 16 * p + g;
    int b = m >> 11, s = m & 2047;
    int hh = n0 >> 7, dbase = half << 6;
    float* dst = O + ((size_t)((b * NHEAD + hh) * S_LEN + s) * DHEAD);
    if (perm) {
        #pragma unroll
        for (int nb = 0; nb < 8; nb++) {
            int d0 = dbase + nb * 8 + 2 * t, d1 = d0 + 1;
            int p0 = permd(d0), p1 = permd(d1);
            dst[p0] = acc[nb][0];
            dst[p1] = acc[nb][1];
            dst[8 * DHEAD + p0] = acc[nb][2];
            dst[8 * DHEAD + p1] = acc[nb][3];
        }
    } else {
        #pragma unroll
        for (int nb = 0; nb < 8; nb++) {
            int d = dbase + nb * 8 + 2 * t;
            *(float2*)(dst + d) = make_float2(acc[nb][0], acc[nb][1]);
            *(float2*)(dst + 8 * DHEAD + d) = make_float2(acc[nb][2], acc[nb][3]);
        }
    }
}

// ---------------------------------------------------------------------------
// Windowed attention via tf32 mma. CTA = 128 queries x (head, batch),
// 512 threads = 16 warps = 8 warp-PAIRS; pair p owns query rows 16p..16p+15.
//   even warp of pair: QK keys 0-31,  PV d 0-63
//   odd  warp of pair: QK keys 32-63, PV d 64-127
// Key tiles of 64, double-buffered cp.async. Q/K d-permuted -> LDS.64 frags.
// exp computed on the FMA pipe (exp2 poly) -- MUFU was the binder.
// ---------------------------------------------------------------------------
#define KSTR 136
#define VSTR 136
#define PSTR 68
// smem float offsets
#define SKB0 0
#define SKB1 (64*KSTR)                    // 8704
#define SVB0 (2*64*KSTR)                  // 17408
#define SVB1 (2*64*KSTR + 64*VSTR)        // 26112
#define SQS  (2*64*KSTR + 2*64*VSTR)      // 34816  Q staging; P pair bufs after qa load
#define SEMB (SQS + 128*KSTR)             // 52224
#define SLS  (SEMB + 512)                 // 52736  row-sum exchange [8][2][16]
#define STOT (SLS + 256)                  // 52992 floats = 211968 B

__device__ __forceinline__ void cp_kv512(const float* __restrict__ Kh,
                                         const float* __restrict__ Vh, int row0,
                                         uint32_t kdst, uint32_t vdst, int tid) {
    int r = tid >> 3, c0 = (tid & 7) << 4;
    const float* ks = Kh + (size_t)(row0 + r) * DHEAD + c0;
    const float* vs = Vh + (size_t)(row0 + r) * DHEAD + c0;
    uint32_t kd = kdst + (uint32_t)(r * KSTR + c0) * 4u;
    uint32_t vd = vdst + (uint32_t)(r * VSTR + c0) * 4u;
    #pragma unroll
    for (int i = 0; i < 4; i++) {
        cpasync16(kd + i * 16, ks + i * 4);
        cpasync16(vd + i * 16, vs + i * 4);
    }
}

// exp(score*QK_SCALE + emb) computed as 2^(score*QK_SL2E + emb*LOG2E) with a
// degree-5 poly on the FMA/ALU pipes (no MUFU). embS holds emb*LOG2E.
// Masked lanes clamp to ~2^-126 (~1e-38) -- negligible vs row sums.
__device__ __forceinline__ float pcalc(float a, int d, const float* __restrict__ embS) {
    if (d < 0) return 0.f;                      // causal+rpe masked
    unsigned u = (unsigned)(d - 1);
    float bias = (u < 511u) ? embS[u] : -2e9f;  // out of window / diagonal
    float y = fmaf(a, QK_SL2E, bias);
    y = fmaxf(y, -126.f);
    float rr = y + 12582912.f;                  // 1.5*2^23 round-to-int magic
    float f = y - (rr - 12582912.f);            // f in [-0.5, 0.5]
    int   n = __float_as_int(rr) << 23;         // integer part into exponent
    float pp =         1.8775767e-3f;
    pp = fmaf(pp, f,   8.9893397e-3f);
    pp = fmaf(pp, f,   5.5826318e-2f);
    pp = fmaf(pp, f,   2.4015361e-1f);
    pp = fmaf(pp, f,   6.9315308e-1f);
    pp = fmaf(pp, f,   1.0f);
    return __int_as_float(__float_as_int(pp) + n);
}

__global__ __launch_bounds__(512, 1) void attn_mma(
    const float* __restrict__ emb, float* __restrict__ out)
{
    extern __shared__ float sm[];
    float* embS = sm + SEMB;
    uint32_t smb = (uint32_t)__cvta_generic_to_shared(sm);

    int tid = threadIdx.x;
    int lane = tid & 31, w = tid >> 5, g = lane >> 2, t = lane & 3;
    int p = w >> 1, half = w & 1;
    // heavy-first launch order: x=0..11 -> qt 4..15 (T=10), x=12..15 -> qt 0..3
    int qt = (blockIdx.x + 4) & 15;
    int qs = qt << 7, h = blockIdx.y, b = blockIdx.z;
    size_t ho = (size_t)(b * NHEAD + h) * S_LEN * DHEAD;
    const float* Qh = g_Qp + ho;
    const float* Kh = g_Kp + ho;
    const float* Vh = g_Vp + ho;

    int kt_lo = (qs >= WIN) ? ((qs - WIN) >> 6) : 0;
    int kt_hi = (qs + 127) >> 6;
    int T = kt_hi - kt_lo + 1;

    // prefetch tile 0 into buffer 0
    cp_kv512(Kh, Vh, kt_lo << 6, smb + SKB0 * 4, smb + SVB0 * 4, tid);
    CP_COMMIT();

    for (int i = tid; i < 512; i += 512) embS[i] = emb[i] * LOG2E;

    // stage Q tile (tf32 RN; source already d-permuted)
    {
        int r = tid >> 2, kc = (tid & 3) << 5;
        const float* src = Qh + (size_t)(qs + r) * DHEAD + kc;
        #pragma unroll
        for (int i = 0; i < 8; i++)
            *(uint4*)&sm[SQS + r * KSTR + kc + i * 4] = cvt4(*(const float4*)(src + i * 4));
    }
    __syncthreads();

    // Q A-frags, persistent (LDS.64 on permuted pairs)
    uint32_t qa[16][4];
    {
        const float* ab = sm + SQS + (16 * p + g) * KSTR;
        #pragma unroll
        for (int ks = 0; ks < 16; ks++) {
            uint2 u0 = *(const uint2*)&ab[ks * 8 + 2 * t];
            uint2 u1 = *(const uint2*)&ab[8 * KSTR + ks * 8 + 2 * t];
            qa[ks][0] = u0.x; qa[ks][1] = u1.x; qa[ks][2] = u0.y; qa[ks][3] = u1.y;
        }
    }
    CP_WAIT0();
    __syncthreads();   // buf0 ready; all qa loaded -> Q region reusable as P

    float* Ps = sm + SQS + p * (16 * PSTR);   // per-PAIR P buffer [16][68]

    float oacc[8][4];
    #pragma unroll
    for (int nb = 0; nb < 8; nb++)
        #pragma unroll
        for (int e = 0; e < 4; e++) oacc[nb][e] = 0.f;
    float sum0 = 0.f, sum1 = 0.f;

    int r_lo = qs + 16 * p, r_hi = r_lo + 15;
    int r0 = r_lo + g;
    int nbq = half << 2;     // QK key-block offset (nb 0-3 / 4-7)
    int dvo = half << 6;     // PV d offset (0 / 64)

    for (int i = 0; i < T; i++) {
        int ks0 = (kt_lo + i) << 6;
        const float* kb = sm + ((i & 1) ? SKB1 : SKB0);
        const float* vb = sm + ((i & 1) ? SVB1 : SVB0);
        bool hasnext = (i + 1 < T);
        bool active = (ks0 <= r_hi) && (ks0 + 63 >= r_lo - WIN);

        if (hasnext) {
            cp_kv512(Kh, Vh, (kt_lo + i + 1) << 6,
                     smb + 4u * ((i & 1) ? SKB0 : SKB1),
                     smb + 4u * ((i & 1) ? SVB0 : SVB1), tid);
            CP_COMMIT();
        }

        if (active) {
            // --- QK: S[16 x 32] (this warp's key half) ---
            float acc[4][4];
            #pragma unroll
            for (int nb = 0; nb < 4; nb++)
                #pragma unroll
                for (int e = 0; e < 4; e++) acc[nb][e] = 0.f;
            #pragma unroll
            for (int ks = 0; ks < 16; ks++) {
                #pragma unroll
                for (int nb = 0; nb < 4; nb++) {
                    uint2 bu = *(const uint2*)&kb[((nbq + nb) * 8 + g) * KSTR + ks * 8 + 2 * t];
                    mma8(acc[nb], qa[ks], bu.x, bu.y);
                }
            }

            // --- softmax (FMA-pipe exp2) + P store into pair buffer ---
            #pragma unroll
            for (int nb = 0; nb < 4; nb++) {
                int j0 = ks0 + (nbq + nb) * 8 + 2 * t;
                int d00 = r0 - j0;
                float p00 = pcalc(acc[nb][0], d00,     embS);
                float p01 = pcalc(acc[nb][1], d00 - 1, embS);
                float p10 = pcalc(acc[nb][2], d00 + 8, embS);
                float p11 = pcalc(acc[nb][3], d00 + 7, embS);
                sum0 += p00 + p01;
                sum1 += p10 + p11;
                int c = (nbq + nb) * 8 + 2 * t;
                *(uint2*)&Ps[g * PSTR + c] = make_uint2(tf32r(p00), tf32r(p01));
                *(uint2*)&Ps[(g + 8) * PSTR + c] = make_uint2(tf32r(p10), tf32r(p11));
            }
            asm volatile("bar.sync %0, %1;" :: "r"(p + 1), "r"(64) : "memory");

            // --- PV: O[16 x 64] (this warp's d half) over all 64 keys ---
            #pragma unroll
            for (int ks = 0; ks < 8; ks++) {
                uint32_t pa[4];
                pa[0] = __float_as_uint(Ps[g * PSTR + ks * 8 + t]);
                pa[1] = __float_as_uint(Ps[(g + 8) * PSTR + ks * 8 + t]);
                pa[2] = __float_as_uint(Ps[g * PSTR + ks * 8 + t + 4]);
                pa[3] = __float_as_uint(Ps[(g + 8) * PSTR + ks * 8 + t + 4]);
                const float* bv = vb + (ks * 8 + t) * VSTR + dvo + g;
                #pragma unroll
                for (int nb = 0; nb < 8; nb++) {
                    uint32_t b0 = __float_as_uint(bv[nb * 8]);
                    uint32_t b1 = __float_as_uint(bv[4 * VSTR + nb * 8]);
                    mma8(oacc[nb], pa, b0, b1);
                }
            }
        }

        if (hasnext) CP_WAIT0();
        __syncthreads();   // K/V buffer swap + P overwrite hazard
    }

    // row sums: quad-reduce then combine the two key-halves via smem
    sum0 += __shfl_xor_sync(0xffffffffu, sum0, 1);
    sum0 += __shfl_xor_sync(0xffffffffu, sum0, 2);
    sum1 += __shfl_xor_sync(0xffffffffu, sum1, 1);
    sum1 += __shfl_xor_sync(0xffffffffu, sum1, 2);
    float* ls = sm + SLS;
    if (t == 0) {
        ls[(p * 2 + half) * 16 + g] = sum0;
        ls[(p * 2 + half) * 16 + g + 8] = sum1;
    }
    __syncthreads();
    float linv0 = 1.f / (ls[p * 32 + g] + ls[p * 32 + 16 + g]);
    float linv1 = 1.f / (ls[p * 32 + g + 8] + ls[p * 32 + 16 + g + 8]);

    // epilogue: out[b][s][h*128+d]; row 0 (fully masked) = V[0]
    float* dst0 = out + ((size_t)(b * S_LEN + r0) * (NHEAD * DHEAD)) + h * DHEAD + dvo + 2 * t;
    #pragma unroll
    for (int nb = 0; nb < 8; nb++) {
        float2 v0;
        if (r0 == 0) v0 = make_float2(Vh[dvo + nb * 8 + 2 * t], Vh[dvo + nb * 8 + 2 * t + 1]);
        else         v0 = make_float2(oacc[nb][0] * linv0, oacc[nb][1] * linv0);
        *(float2*)(dst0 + nb * 8) = v0;
        *(float2*)(dst0 + 8 * (NHEAD * DHEAD) + nb * 8) =
            make_float2(oacc[nb][2] * linv1, oacc[nb][3] * linv1);
    }
}

extern "C" void kernel_launch(void* const* d_in, const int* in_sizes, int n_in,
                              void* d_out, int out_size)
{
    (void)in_sizes; (void)n_in; (void)out_size;
    const float* q   = (const float*)d_in[0];
    const float* k   = (const float*)d_in[1];
    const float* v   = (const float*)d_in[2];
    const float* Wq  = (const float*)d_in[3];
    const float* Wk  = (const float*)d_in[4];
    const float* Wv  = (const float*)d_in[5];
    const float* emb = (const float*)d_in[6];
    float* out = (float*)d_out;

    int proj_smem = (128 * PX_STR + WS_SIZE) * 4;
    cudaFuncSetAttribute(proj_mma, cudaFuncAttributeMaxDynamicSharedMemorySize, proj_smem);
    cudaFuncSetAttribute(attn_mma, cudaFuncAttributeMaxDynamicSharedMemorySize, STOT * 4);

    proj_mma<<<dim3(32, 8, 3), 512, proj_smem>>>(q, k, v, Wq, Wk, Wv);
    attn_mma<<<dim3(16, NHEAD, NB), 512, STOT * 4>>>(emb, out);
}